// round 14
// baseline (speedup 1.0000x reference)
#include <cuda_runtime.h>
#include <cuda_bf16.h>
#include <math.h>
#include <stdint.h>

#define Bc   64
#define Nc   2048
#define Dc   256
#define Hc   64
#define NBc  3
#define Mc   (Bc * Nc)
#define KTOP 204
#define K5   102
#define TWOD 512
#define CATD 1280
#define NEG_INF_F (-1e30f)

#define OUT_BAG   0
#define OUT_ALLA  (OUT_BAG  + Bc * TWOD)
#define OUT_AVG   (OUT_ALLA + Bc * NBc * Nc)
#define OUT_TOPK  (OUT_AVG  + Bc * Nc)
#define OUT_ENT   (OUT_TOPK + Bc * Nc)
#define OUT_EFF   (OUT_ENT  + Bc)
#define OUT_T5    (OUT_EFF  + Bc)

// ---- GEMM smem layout (R11 2-CTA form) ----
#define B_BUF_B    15360
#define A_LIMB_B   10240
#define SB_A       30720
#define SB_SCAL    51200
#define SMEM_DYN   (51200 + 2048)
#define NSEG       8

// ---------------- device scratch ----------------
__device__ __nv_bfloat16 g_B[8 * 320 * 32];   // [chunk][row: 256 b1 + 64 b2scorer][k]
__device__ float g_b1c[256];
__device__ float g_w2c[256];
__device__ float g_b2c[4];
__device__ float g_scores[4L * Mc];           // [group][m]
__device__ float g_poolw[(long)Bc * 5 * Nc];
__device__ float g_poolpart[Bc * NSEG * 5 * 256];
__device__ float g_fpart[Bc * 4 * TWOD];

// ---------------- helpers ----------------
__device__ __forceinline__ uint32_t smem_u32(const void* p) {
    uint32_t a;
    asm("{ .reg .u64 t; cvta.to.shared.u64 t, %1; cvt.u32.u64 %0, t; }" : "=r"(a) : "l"(p));
    return a;
}
__device__ __forceinline__ void ldsm_x4(uint32_t* r, uint32_t addr) {
    asm volatile("ldmatrix.sync.aligned.m8n8.x4.shared.b16 {%0,%1,%2,%3}, [%4];"
        : "=r"(r[0]), "=r"(r[1]), "=r"(r[2]), "=r"(r[3]) : "r"(addr));
}
__device__ __forceinline__ void mma16816(float* d, const uint32_t* a, const uint32_t* b) {
    asm volatile(
        "mma.sync.aligned.m16n8k16.row.col.f32.bf16.bf16.f32 "
        "{%0,%1,%2,%3}, {%4,%5,%6,%7}, {%8,%9}, {%0,%1,%2,%3};"
        : "+f"(d[0]), "+f"(d[1]), "+f"(d[2]), "+f"(d[3])
        : "r"(a[0]), "r"(a[1]), "r"(a[2]), "r"(a[3]), "r"(b[0]), "r"(b[1]));
}
#define CP16(dst, src) asm volatile("cp.async.cg.shared.global [%0], [%1], 16;" :: "r"(dst), "l"(src))
#define CP_COMMIT()    asm volatile("cp.async.commit_group;" ::: "memory")
#define CP_WAIT(n)     asm volatile("cp.async.wait_group %0;" :: "n"(n) : "memory")

__device__ __forceinline__ float tanh_fast(float x) {
    float y;
    asm("tanh.approx.f32 %0, %1;" : "=f"(y) : "f"(x));
    return y;
}
__device__ __forceinline__ unsigned f2key(float f) {
    unsigned u = __float_as_uint(f);
    return (u & 0x80000000u) ? ~u : (u | 0x80000000u);
}
__device__ __forceinline__ float key2f(unsigned k) {
    unsigned u = (k & 0x80000000u) ? (k & 0x7FFFFFFFu) : ~k;
    return __uint_as_float(u);
}

// ---- 1024-thread block reductions (warp shuffle, two-level) ----
__device__ __forceinline__ float bsum1024(float v, float* sw) {
    int lane = threadIdx.x & 31, wid = threadIdx.x >> 5;
    #pragma unroll
    for (int o = 16; o; o >>= 1) v += __shfl_xor_sync(0xffffffffu, v, o);
    if (!lane) sw[wid] = v;
    __syncthreads();
    if (wid == 0) {
        float x = sw[lane];
        #pragma unroll
        for (int o = 16; o; o >>= 1) x += __shfl_xor_sync(0xffffffffu, x, o);
        if (!lane) sw[32] = x;
    }
    __syncthreads();
    float r = sw[32];
    __syncthreads();
    return r;
}
template<int NV>
__device__ __forceinline__ void bsumv(float* v, float* sw) {
    int lane = threadIdx.x & 31, wid = threadIdx.x >> 5;
    #pragma unroll
    for (int o = 16; o; o >>= 1)
        #pragma unroll
        for (int i = 0; i < NV; i++) v[i] += __shfl_xor_sync(0xffffffffu, v[i], o);
    if (!lane)
        #pragma unroll
        for (int i = 0; i < NV; i++) sw[i * 33 + wid] = v[i];
    __syncthreads();
    if (wid == 0) {
        float x[NV];
        #pragma unroll
        for (int i = 0; i < NV; i++) x[i] = sw[i * 33 + lane];
        #pragma unroll
        for (int o = 16; o; o >>= 1)
            #pragma unroll
            for (int i = 0; i < NV; i++) x[i] += __shfl_xor_sync(0xffffffffu, x[i], o);
        if (!lane)
            #pragma unroll
            for (int i = 0; i < NV; i++) sw[i * 33 + 32] = x[i];
    }
    __syncthreads();
    #pragma unroll
    for (int i = 0; i < NV; i++) v[i] = sw[i * 33 + 32];
    __syncthreads();
}
template<int NV>
__device__ __forceinline__ void bmaxv(float* v, float* sw) {
    int lane = threadIdx.x & 31, wid = threadIdx.x >> 5;
    #pragma unroll
    for (int o = 16; o; o >>= 1)
        #pragma unroll
        for (int i = 0; i < NV; i++) v[i] = fmaxf(v[i], __shfl_xor_sync(0xffffffffu, v[i], o));
    if (!lane)
        #pragma unroll
        for (int i = 0; i < NV; i++) sw[i * 33 + wid] = v[i];
    __syncthreads();
    if (wid == 0) {
        float x[NV];
        #pragma unroll
        for (int i = 0; i < NV; i++) x[i] = sw[i * 33 + lane];
        #pragma unroll
        for (int o = 16; o; o >>= 1)
            #pragma unroll
            for (int i = 0; i < NV; i++) x[i] = fmaxf(x[i], __shfl_xor_sync(0xffffffffu, x[i], o));
        if (!lane)
            #pragma unroll
            for (int i = 0; i < NV; i++) sw[i * 33 + 32] = x[i];
    }
    __syncthreads();
    #pragma unroll
    for (int i = 0; i < NV; i++) v[i] = sw[i * 33 + 32];
    __syncthreads();
}
__device__ __forceinline__ int bisum1024(int v, int* sw) {
    int lane = threadIdx.x & 31, wid = threadIdx.x >> 5;
    #pragma unroll
    for (int o = 16; o; o >>= 1) v += __shfl_xor_sync(0xffffffffu, v, o);
    if (!lane) sw[wid] = v;
    __syncthreads();
    if (wid == 0) {
        int x = sw[lane];
        #pragma unroll
        for (int o = 16; o; o >>= 1) x += __shfl_xor_sync(0xffffffffu, x, o);
        if (!lane) sw[32] = x;
    }
    __syncthreads();
    int r = sw[32];
    __syncthreads();
    return r;
}
__device__ __forceinline__ int bexscan1024(int v, int* sw) {
    int lane = threadIdx.x & 31, wid = threadIdx.x >> 5;
    int x = v;
    #pragma unroll
    for (int o = 1; o < 32; o <<= 1) {
        int y = __shfl_up_sync(0xffffffffu, x, o);
        if (lane >= o) x += y;
    }
    if (lane == 31) sw[wid] = x;
    __syncthreads();
    if (wid == 0) {
        int w = sw[lane], inc = w;
        #pragma unroll
        for (int o = 1; o < 32; o <<= 1) {
            int y = __shfl_up_sync(0xffffffffu, inc, o);
            if (lane >= o) inc += y;
        }
        sw[lane] = inc - w;
    }
    __syncthreads();
    int r = sw[wid] + x - v;
    __syncthreads();
    return r;
}

// exact K-th largest among 2048 keys; 1024 threads, 2 keys each.
__device__ unsigned radix1024(const unsigned* keys, int K,
                              unsigned* hist, volatile unsigned* bc) {
    const int t = threadIdx.x;
    const int n0 = t * 2;
    unsigned prefix = 0;
    int rem = K;
    for (int pass = 0; pass < 4; pass++) {
        const int shift = 24 - 8 * pass;
        const unsigned hm = pass ? (0xFFFFFFFFu << (shift + 8)) : 0u;
        if (t < 256) hist[t] = 0;
        __syncthreads();
        #pragma unroll
        for (int q = 0; q < 2; q++) {
            unsigned u = keys[n0 + q];
            if ((u & hm) == prefix) atomicAdd(&hist[(u >> shift) & 255u], 1u);
        }
        __syncthreads();
        if (t < 32) {
            int base = t * 8;
            int v[8], s = 0;
            #pragma unroll
            for (int i = 0; i < 8; i++) { v[i] = (int)hist[255 - (base + i)]; s += v[i]; }
            int inc = s;
            #pragma unroll
            for (int o = 1; o < 32; o <<= 1) {
                int y = __shfl_up_sync(0xffffffffu, inc, o);
                if (t >= o) inc += y;
            }
            int run = inc - s;
            #pragma unroll
            for (int i = 0; i < 8; i++) {
                int prev = run;
                run += v[i];
                if (run >= rem && prev < rem) {
                    bc[0] = prefix | ((unsigned)(255 - (base + i)) << shift);
                    bc[1] = (unsigned)(rem - prev);
                }
            }
        }
        __syncthreads();
        prefix = bc[0];
        rem = (int)bc[1];
        __syncthreads();
    }
    return prefix;
}

// ---------------- K0: weight image + scalars ----------------
__global__ void k_prep(const float* __restrict__ Ws1, const float* __restrict__ Wa1,
                       const float* __restrict__ bs1, const float* __restrict__ Ws2,
                       const float* __restrict__ bs2, const float* __restrict__ ba1,
                       const float* __restrict__ Wa2, const float* __restrict__ ba2) {
    if (blockIdx.x == 320) {
        int t = threadIdx.x;
        int g = t >> 6, ch = t & 63;
        g_b1c[t] = (g == 0) ? bs1[ch] : ba1[(g - 1) * Hc + ch];
        g_w2c[t] = (g == 0) ? Ws2[ch] : Wa2[(g - 1) * Hc + ch];
        if (t < 4) g_b2c[t] = (t == 0) ? bs2[0] : ba2[t - 1];
        return;
    }
    int gid = blockIdx.x * 256 + threadIdx.x;   // < 81920
    int k = gid & 31;
    int row = (gid >> 5) % 320;
    int c = gid / 10240;                        // chunk
    int kg = c * 32 + k;
    float w;
    bool resid = (row >= 256);
    int n = resid ? (row - 256) : row;
    if (n < 64) w = Ws1[kg * 64 + n];
    else {
        int br = (n - 64) >> 6, h = (n - 64) & 63;
        w = Wa1[(br * 256 + kg) * 64 + h];
    }
    __nv_bfloat16 h1 = __float2bfloat16(w);
    __nv_bfloat16 v = resid ? __float2bfloat16(w - __bfloat162float(h1)) : h1;
    g_B[gid] = v;
}

// ---------------- K1: split-bf16 HMMA scorer GEMM (exact R11 2-CTA form) ----------------
__global__ void __launch_bounds__(256, 2) k_gemm_mma(const float* __restrict__ X) {
    extern __shared__ char sm[];
    const int tid = threadIdx.x;
    const int lane = tid & 31;
    const int wid = tid >> 5;
    const int wm = wid & 3;
    const int wn = wid >> 2;
    const int m0g = blockIdx.y * 128;
    const int ct = blockIdx.x;
    const uint32_t sb = smem_u32(sm);
    float* sb1 = (float*)(sm + SB_SCAL);
    float* sw2 = sb1 + 256;

    sb1[tid] = g_b1c[tid];
    sw2[tid] = g_w2c[tid];

    float acc[2][8][4];
    #pragma unroll
    for (int i = 0; i < 2; i++)
        #pragma unroll
        for (int j = 0; j < 8; j++)
            #pragma unroll
            for (int e = 0; e < 4; e++) acc[i][j][e] = 0.f;

    const char* gB = (const char*)g_B;
    const bool heavy = (ct == 0) && (wn == 0);

    auto stage_B = [&](int c, int buf) {
        uint32_t dbase = sb + buf * B_BUF_B;
        #pragma unroll
        for (int i = 0; i < 2; i++) {
            int flat = tid + i * 256;
            int u = flat & 3;
            int n = flat >> 2;
            uint32_t dst = dbase + n * 80 + u * 16;
            const char* src = gB + (size_t)((c * 320 + ct * 128 + n) * 64 + u * 16);
            CP16(dst, src);
        }
        if (ct == 0) {
            int u = tid & 3;
            int n = tid >> 2;
            uint32_t dst = dbase + (128 + n) * 80 + u * 16;
            const char* src = gB + (size_t)((c * 320 + 256 + n) * 64 + u * 16);
            CP16(dst, src);
        }
    };

    float4 av[4];
    auto load_x = [&](int c) {
        #pragma unroll
        for (int q = 0; q < 4; q++) {
            int row = q * 32 + (tid >> 3);
            int col = (tid & 7) * 4 + c * 32;
            av[q] = *(const float4*)(X + (size_t)(m0g + row) * 256 + col);
        }
    };
    auto convert_a = [&]() {
        #pragma unroll
        for (int q = 0; q < 4; q++) {
            int row = q * 32 + (tid >> 3);
            uint32_t off = row * 80 + (tid & 7) * 8;
            float v[4] = {av[q].x, av[q].y, av[q].z, av[q].w};
            unsigned short s1[4], s2[4];
            #pragma unroll
            for (int e = 0; e < 4; e++) {
                __nv_bfloat16 h1 = __float2bfloat16(v[e]);
                __nv_bfloat16 h2 = __float2bfloat16(v[e] - __bfloat162float(h1));
                s1[e] = __bfloat16_as_ushort(h1);
                s2[e] = __bfloat16_as_ushort(h2);
            }
            *(uint2*)(sm + SB_A + off) =
                make_uint2((unsigned)s1[0] | ((unsigned)s1[1] << 16),
                           (unsigned)s1[2] | ((unsigned)s1[3] << 16));
            if (ct == 0)
                *(uint2*)(sm + SB_A + A_LIMB_B + off) =
                    make_uint2((unsigned)s2[0] | ((unsigned)s2[1] << 16),
                               (unsigned)s2[2] | ((unsigned)s2[3] << 16));
        }
    };

    stage_B(0, 0); CP_COMMIT();
    load_x(0);

    for (int c = 0; c < 8; c++) {
        if (c < 7) { stage_B(c + 1, (c + 1) & 1); CP_COMMIT(); }
        convert_a();
        if (c < 7) load_x(c + 1);
        if (c < 7) { CP_WAIT(1); } else { CP_WAIT(0); }
        __syncthreads();

        uint32_t bbuf = sb + (c & 1) * B_BUF_B;
        #pragma unroll
        for (int ks = 0; ks < 2; ks++) {
            uint32_t acol = ks * 32 + ((lane >> 4) & 1) * 16;
            uint32_t arow = (wm * 32 + (lane & 15)) * 80;
            uint32_t arow2 = (wm * 32 + 16 + (lane & 15)) * 80;
            uint32_t a1r0[4], a1r1[4], a2r0[4], a2r1[4];
            ldsm_x4(a1r0, sb + SB_A + arow + acol);
            ldsm_x4(a1r1, sb + SB_A + arow2 + acol);
            if (heavy) {
                ldsm_x4(a2r0, sb + SB_A + A_LIMB_B + arow + acol);
                ldsm_x4(a2r1, sb + SB_A + A_LIMB_B + arow2 + acol);
            }
            const uint32_t koff = ks * 32 + ((lane >> 3) & 1) * 16;
            #pragma unroll
            for (int jj = 0; jj < 4; jj++) {
                uint32_t bfr[4];
                int rowb = wn * 64 + jj * 16 + ((lane >> 4) & 1) * 8 + (lane & 7);
                ldsm_x4(bfr, bbuf + rowb * 80 + koff);
                mma16816(acc[0][jj * 2],     a1r0, bfr);
                mma16816(acc[1][jj * 2],     a1r1, bfr);
                mma16816(acc[0][jj * 2 + 1], a1r0, bfr + 2);
                mma16816(acc[1][jj * 2 + 1], a1r1, bfr + 2);
                if (heavy) {
                    mma16816(acc[0][jj * 2],     a2r0, bfr);
                    mma16816(acc[1][jj * 2],     a2r1, bfr);
                    mma16816(acc[0][jj * 2 + 1], a2r0, bfr + 2);
                    mma16816(acc[1][jj * 2 + 1], a2r1, bfr + 2);
                    uint32_t bfr2[4];
                    int rowb2 = 128 + jj * 16 + ((lane >> 4) & 1) * 8 + (lane & 7);
                    ldsm_x4(bfr2, bbuf + rowb2 * 80 + koff);
                    mma16816(acc[0][jj * 2],     a1r0, bfr2);
                    mma16816(acc[1][jj * 2],     a1r1, bfr2);
                    mma16816(acc[0][jj * 2 + 1], a1r0, bfr2 + 2);
                    mma16816(acc[1][jj * 2 + 1], a1r1, bfr2 + 2);
                }
            }
        }
        __syncthreads();
    }

    const int g = ct * 2 + wn;
    const bool is_relu = (g == 0);
    const int cbase = ct * 128 + wn * 64;
    const float b2 = g_b2c[g];

    #pragma unroll
    for (int mf = 0; mf < 2; mf++) {
        float p0 = 0.f, p1 = 0.f;
        #pragma unroll
        for (int j = 0; j < 8; j++) {
            int c0 = cbase + j * 8 + (lane & 3) * 2;
            float v0 = acc[mf][j][0] + sb1[c0];
            float v1 = acc[mf][j][1] + sb1[c0 + 1];
            float v2 = acc[mf][j][2] + sb1[c0];
            float v3 = acc[mf][j][3] + sb1[c0 + 1];
            float f0 = is_relu ? fmaxf(v0, 0.f) : tanh_fast(v0);
            float f1 = is_relu ? fmaxf(v1, 0.f) : tanh_fast(v1);
            float f2 = is_relu ? fmaxf(v2, 0.f) : tanh_fast(v2);
            float f3 = is_relu ? fmaxf(v3, 0.f) : tanh_fast(v3);
            p0 = fmaf(f0, sw2[c0], p0);
            p0 = fmaf(f1, sw2[c0 + 1], p0);
            p1 = fmaf(f2, sw2[c0], p1);
            p1 = fmaf(f3, sw2[c0 + 1], p1);
        }
        p0 += __shfl_xor_sync(0xffffffff, p0, 1);
        p0 += __shfl_xor_sync(0xffffffff, p0, 2);
        p1 += __shfl_xor_sync(0xffffffff, p1, 1);
        p1 += __shfl_xor_sync(0xffffffff, p1, 2);
        if ((lane & 3) == 0) {
            int m = m0g + wm * 32 + mf * 16 + (lane >> 2);
            g_scores[(size_t)g * Mc + m]     = p0 + b2;
            g_scores[(size_t)g * Mc + m + 8] = p1 + b2;
        }
    }
}

// ---------------- K2: per-batch top-k, softmax, diagnostics (1024 thr) ----------------
__global__ void __launch_bounds__(1024) k_perbatch(const float* __restrict__ mask,
                                                   float* __restrict__ out) {
    const int b = blockIdx.x;
    const int t = threadIdx.x;
    const int n0 = t * 2;

    __shared__ unsigned s_key[2048];
    __shared__ unsigned s_hist[256];
    __shared__ float    s_wf[3 * 33];
    __shared__ int      s_wi[33];
    __shared__ unsigned s_bc[2];

    float mk[2];
    mk[0] = mask[b * Nc + n0];
    mk[1] = mask[b * Nc + n0 + 1];

    float cnt = bsum1024(mk[0] + mk[1], s_wf);
    float inv_mean = 1.f / fmaxf(cnt, 1.f);

    #pragma unroll
    for (int q = 0; q < 2; q++) {
        float sc = g_scores[(size_t)b * Nc + n0 + q];
        if (mk[q] == 0.f) sc = NEG_INF_F;
        s_key[n0 + q] = f2key(sc);
    }
    __syncthreads();

    unsigned T = radix1024(s_key, KTOP, s_hist, s_bc);

    int lg = 0, le = 0;
    unsigned uk[2];
    #pragma unroll
    for (int q = 0; q < 2; q++) {
        uk[q] = s_key[n0 + q];
        lg += (uk[q] > T);
        le += (uk[q] == T);
    }
    int cg = bisum1024(lg, s_wi);
    int need = KTOP - cg;
    int excl = bexscan1024(le, s_wi);

    float tmv[2];
    float lc = 0.f;
    int rank = excl;
    #pragma unroll
    for (int q = 0; q < 2; q++) {
        float tmq = 0.f;
        if (uk[q] > T) tmq = 1.f;
        else if (uk[q] == T) { if (rank < need) tmq = 1.f; rank++; }
        tmv[q] = tmq;
        out[OUT_TOPK + b * Nc + n0 + q] = tmq;
        lc += tmq * mk[q];
    }
    float csum = bsum1024(lc, s_wf);
    float invden = 1.f / fmaxf(csum, 1.f);
    #pragma unroll
    for (int q = 0; q < 2; q++) {
        g_poolw[((size_t)b * 5 + 0) * Nc + n0 + q] = mk[q] * inv_mean;
        g_poolw[((size_t)b * 5 + 1) * Nc + n0 + q] = tmv[q] * mk[q] * invden;
    }

    float sc3[3][2];
    float lm[3] = {-3e38f, -3e38f, -3e38f};
    #pragma unroll
    for (int k = 0; k < 3; k++)
        #pragma unroll
        for (int q = 0; q < 2; q++) {
            float s = g_scores[(size_t)(1 + k) * Mc + b * Nc + n0 + q];
            if (mk[q] == 0.f) s = NEG_INF_F;
            sc3[k][q] = s;
            lm[k] = fmaxf(lm[k], s);
        }
    bmaxv<3>(lm, s_wf);
    float ls[3] = {0.f, 0.f, 0.f};
    #pragma unroll
    for (int k = 0; k < 3; k++)
        #pragma unroll
        for (int q = 0; q < 2; q++) {
            sc3[k][q] = expf(sc3[k][q] - lm[k]);
            ls[k] += sc3[k][q];
        }
    bsumv<3>(ls, s_wf);

    float avq[2] = {0.f, 0.f};
    #pragma unroll
    for (int k = 0; k < 3; k++) {
        float inv = 1.f / ls[k];
        #pragma unroll
        for (int q = 0; q < 2; q++) {
            float a = (mk[q] == 0.f) ? 0.f : sc3[k][q] * inv;
            out[OUT_ALLA + ((size_t)b * NBc + k) * Nc + n0 + q] = a;
            g_poolw[((size_t)b * 5 + 2 + k) * Nc + n0 + q] = a;
            avq[q] += a;
        }
    }
    #pragma unroll
    for (int q = 0; q < 2; q++) avq[q] *= (1.f / 3.f);

    float es[2] = {0.f, 0.f};
    #pragma unroll
    for (int q = 0; q < 2; q++) {
        out[OUT_AVG + b * Nc + n0 + q] = avq[q];
        es[0] += avq[q] * logf(avq[q] + 1e-8f);
        es[1] += avq[q] * avq[q];
        s_key[n0 + q] = f2key(avq[q]);
    }
    bsumv<2>(es, s_wf);   // also fences s_key writes
    if (t == 0) {
        out[OUT_ENT + b] = -es[0];
        out[OUT_EFF + b] = 1.f / es[1];
    }
    __syncthreads();

    unsigned T5 = radix1024(s_key, K5, s_hist, s_bc);
    int lg5 = 0;
    float lsum5 = 0.f;
    #pragma unroll
    for (int q = 0; q < 2; q++) {
        unsigned u = s_key[n0 + q];
        if (u > T5) { lg5++; lsum5 += avq[q]; }
    }
    int cg5 = bisum1024(lg5, s_wi);
    float sgt = bsum1024(lsum5, s_wf);
    if (t == 0)
        out[OUT_T5 + b] = sgt + (float)(K5 - cg5) * key2f(T5);
}

// ---------------- K3: pooling (exact R8/R11 version) ----------------
__global__ void __launch_bounds__(256) k_pool2(const float* __restrict__ X) {
    const int b = blockIdx.x >> 3;
    const int seg = blockIdx.x & 7;
    const int tid = threadIdx.x;
    const int tx = tid & 63;
    const int rg = tid >> 6;
    __shared__ float sw[5][256];
    __shared__ float part[4][5][256];

    #pragma unroll
    for (int p = 0; p < 5; p++)
        sw[p][tid] = g_poolw[((size_t)b * 5 + p) * Nc + seg * 256 + tid];
    __syncthreads();

    const float* xb = X + ((size_t)(b * Nc + seg * 256 + rg * 64)) * Dc + tx * 4;
    float4 a0 = {0,0,0,0}, a1 = {0,0,0,0}, a2 = {0,0,0,0}, a3 = {0,0,0,0}, a4 = {0,0,0,0};
    #pragma unroll 4
    for (int n = 0; n < 64; n++) {
        float4 xv = *(const float4*)(xb + (size_t)n * Dc);
        float w0 = sw[0][rg * 64 + n], w1 = sw[1][rg * 64 + n], w2 = sw[2][rg * 64 + n];
        float w3 = sw[3][rg * 64 + n], w4 = sw[4][rg * 64 + n];
        a0.x = fmaf(xv.x, w0, a0.x); a0.y = fmaf(xv.y, w0, a0.y);
        a0.z = fmaf(xv.z, w0, a0.z); a0.w = fmaf(xv.w, w0, a0.w);
        a1.x = fmaf(xv.x, w1, a1.x); a1.y = fmaf(xv.y, w1, a1.y);
        a1.z = fmaf(xv.z, w1, a1.z); a1.w = fmaf(xv.w, w1, a1.w);
        a2.x = fmaf(xv.x, w2, a2.x); a2.y = fmaf(xv.y, w2, a2.y);
        a2.z = fmaf(xv.z, w2, a2.z); a2.w = fmaf(xv.w, w2, a2.w);
        a3.x = fmaf(xv.x, w3, a3.x); a3.y = fmaf(xv.y, w3, a3.y);
        a3.z = fmaf(xv.z, w3, a3.z); a3.w = fmaf(xv.w, w3, a3.w);
        a4.x = fmaf(xv.x, w4, a4.x); a4.y = fmaf(xv.y, w4, a4.y);
        a4.z = fmaf(xv.z, w4, a4.z); a4.w = fmaf(xv.w, w4, a4.w);
    }
    *(float4*)&part[rg][0][tx * 4] = a0;
    *(float4*)&part[rg][1][tx * 4] = a1;
    *(float4*)&part[rg][2][tx * 4] = a2;
    *(float4*)&part[rg][3][tx * 4] = a3;
    *(float4*)&part[rg][4][tx * 4] = a4;
    __syncthreads();

    float* dst = g_poolpart + ((size_t)(b * NSEG + seg)) * 1280;
    #pragma unroll
    for (int p = 0; p < 5; p++) {
        float s = part[0][p][tid] + part[1][p][tid] + part[2][p][tid] + part[3][p][tid];
        dst[p * 256 + tid] = s;
    }
}

// ---------------- K4a: fusion GEMV1 partials ----------------
// grid: 16 batch-quads x 4 ksegs x 2 col-halves = 128 blocks, 256 threads.
// 4 batch rows per block halves Wf1 traffic (84 -> 42 MB) while KEEPING 128 blocks.
__global__ void __launch_bounds__(256) k_fuse1(const float* __restrict__ Wf1) {
    const int bq  = blockIdx.x >> 3;          // batch quad 0..15
    const int seg = (blockIdx.x >> 1) & 3;    // kseg 0..3
    const int chf = blockIdx.x & 1;           // col half 0..1
    const int c   = chf * 256 + threadIdx.x;
    const int b0  = bq * 4;
    __shared__ float sc[4][320];

    for (int i = threadIdx.x; i < 320; i += 256) {
        int gi = seg * 320 + i;
        #pragma unroll
        for (int r = 0; r < 4; r++) {
            float s = 0.f;
            #pragma unroll
            for (int se = 0; se < NSEG; se++)
                s += g_poolpart[((size_t)((b0 + r) * NSEG + se)) * 1280 + gi];
            sc[r][i] = s;
        }
    }
    __syncthreads();

    float a0 = 0.f, a1 = 0.f, a2 = 0.f, a3 = 0.f;
    const float* W = Wf1 + (size_t)(seg * 320) * TWOD + c;
    #pragma unroll 8
    for (int j = 0; j < 320; j++) {
        float w = W[(size_t)j * TWOD];
        a0 = fmaf(sc[0][j], w, a0);
        a1 = fmaf(sc[1][j], w, a1);
        a2 = fmaf(sc[2][j], w, a2);
        a3 = fmaf(sc[3][j], w, a3);
    }
    g_fpart[((b0 + 0) * 4 + seg) * TWOD + c] = a0;
    g_fpart[((b0 + 1) * 4 + seg) * TWOD + c] = a1;
    g_fpart[((b0 + 2) * 4 + seg) * TWOD + c] = a2;
    g_fpart[((b0 + 3) * 4 + seg) * TWOD + c] = a3;
}

// ---------------- K4b: reduce + LN + GELU + GEMV2 (2 batch rows per block) ----------------
__global__ void __launch_bounds__(512) k_fuse2(const float* __restrict__ bf1,
                                               const float* __restrict__ lng,
                                               const float* __restrict__ lnb,
                                               const float* __restrict__ Wf2,
                                               const float* __restrict__ bf2,
                                               float* __restrict__ out) {
    const int bp = blockIdx.x;
    const int c = threadIdx.x;
    const int b0 = bp * 2, b1 = b0 + 1;
    __shared__ float sx0[TWOD];
    __shared__ float sx1[TWOD];
    __shared__ float red[TWOD];

    float bb = bf1[c];
    float acc0 = bb, acc1 = bb;
    #pragma unroll
    for (int seg = 0; seg < 4; seg++) {
        acc0 += g_fpart[(b0 * 4 + seg) * TWOD + c];
        acc1 += g_fpart[(b1 * 4 + seg) * TWOD + c];
    }

    float gln = lng[c], bln = lnb[c];

    red[c] = acc0; __syncthreads();
    #pragma unroll
    for (int s = 256; s > 0; s >>= 1) { if (c < s) red[c] += red[c + s]; __syncthreads(); }
    float mu0 = red[0] / (float)TWOD;
    __syncthreads();
    float dv0 = acc0 - mu0;
    red[c] = dv0 * dv0; __syncthreads();
    #pragma unroll
    for (int s = 256; s > 0; s >>= 1) { if (c < s) red[c] += red[c + s]; __syncthreads(); }
    float var0 = red[0] / (float)TWOD;
    __syncthreads();
    float x0 = dv0 * rsqrtf(var0 + 1e-5f) * gln + bln;
    sx0[c] = 0.5f * x0 * (1.f + erff(x0 * 0.70710678118654752f));

    red[c] = acc1; __syncthreads();
    #pragma unroll
    for (int s = 256; s > 0; s >>= 1) { if (c < s) red[c] += red[c + s]; __syncthreads(); }
    float mu1 = red[0] / (float)TWOD;
    __syncthreads();
    float dv1 = acc1 - mu1;
    red[c] = dv1 * dv1; __syncthreads();
    #pragma unroll
    for (int s = 256; s > 0; s >>= 1) { if (c < s) red[c] += red[c + s]; __syncthreads(); }
    float var1 = red[0] / (float)TWOD;
    __syncthreads();
    float x1 = dv1 * rsqrtf(var1 + 1e-5f) * gln + bln;
    sx1[c] = 0.5f * x1 * (1.f + erff(x1 * 0.70710678118654752f));
    __syncthreads();

    float o0 = bf2[c], o1 = o0;
    #pragma unroll 8
    for (int j = 0; j < TWOD; j++) {
        float w = Wf2[(size_t)j * TWOD + c];
        o0 = fmaf(sx0[j], w, o0);
        o1 = fmaf(sx1[j], w, o1);
    }
    out[OUT_BAG + b0 * TWOD + c] = o0;
    out[OUT_BAG + b1 * TWOD + c] = o1;
}

// ---------------- launch ----------------
extern "C" void kernel_launch(void* const* d_in, const int* in_sizes, int n_in,
                              void* d_out, int out_size) {
    const float* inst = (const float*)d_in[0];
    const float* mask = (const float*)d_in[1];
    const float* Ws1 = (const float*)d_in[2];
    const float* bs1 = (const float*)d_in[3];
    const float* Ws2 = (const float*)d_in[4];
    const float* bs2 = (const float*)d_in[5];
    const float* Wa1 = (const float*)d_in[6];
    const float* ba1 = (const float*)d_in[7];
    const float* Wa2 = (const float*)d_in[8];
    const float* ba2 = (const float*)d_in[9];
    const float* Wf1 = (const float*)d_in[10];
    const float* bf1 = (const float*)d_in[11];
    const float* lng = (const float*)d_in[12];
    const float* lnb = (const float*)d_in[13];
    const float* Wf2 = (const float*)d_in[14];
    const float* bf2 = (const float*)d_in[15];
    float* out = (float*)d_out;

    static bool attr_done = false;
    if (!attr_done) {
        cudaFuncSetAttribute(k_gemm_mma, cudaFuncAttributeMaxDynamicSharedMemorySize, SMEM_DYN);
        attr_done = true;
    }

    k_prep<<<321, 256>>>(Ws1, Wa1, bs1, Ws2, bs2, ba1, Wa2, ba2);
    k_gemm_mma<<<dim3(2, Mc / 128), 256, SMEM_DYN>>>(inst);
    k_perbatch<<<Bc, 1024>>>(mask, out);
    k_pool2<<<Bc * NSEG, 256>>>(inst);
    k_fuse1<<<128, 256>>>(Wf1);
    k_fuse2<<<Bc / 2, 512>>>(bf1, lng, lnb, Wf2, bf2, out);
}

// round 15
// speedup vs baseline: 1.0724x; 1.0724x over previous
#include <cuda_runtime.h>
#include <cuda_bf16.h>
#include <math.h>
#include <stdint.h>

#define Bc   64
#define Nc   2048
#define Dc   256
#define Hc   64
#define NBc  3
#define Mc   (Bc * Nc)
#define KTOP 204
#define K5   102
#define TWOD 512
#define CATD 1280
#define NEG_INF_F (-1e30f)

#define OUT_BAG   0
#define OUT_ALLA  (OUT_BAG  + Bc * TWOD)
#define OUT_AVG   (OUT_ALLA + Bc * NBc * Nc)
#define OUT_TOPK  (OUT_AVG  + Bc * Nc)
#define OUT_ENT   (OUT_TOPK + Bc * Nc)
#define OUT_EFF   (OUT_ENT  + Bc)
#define OUT_T5    (OUT_EFF  + Bc)

// ---- GEMM smem layout (R11 2-CTA form) ----
#define B_BUF_B    15360
#define A_LIMB_B   10240
#define SB_A       30720
#define SB_SCAL    51200
#define SMEM_DYN   (51200 + 2048)
#define NSEG       8

// ---------------- device scratch ----------------
__device__ __nv_bfloat16 g_B[8 * 320 * 32];   // [chunk][row: 256 b1 + 64 b2scorer][k]
__device__ float g_b1c[256];
__device__ float g_w2c[256];
__device__ float g_b2c[4];
__device__ float g_scores[4L * Mc];           // [group][m]
__device__ float g_poolw[(long)Bc * 5 * Nc];
__device__ float g_poolpart[Bc * NSEG * 5 * 256];
__device__ float g_fpart[Bc * 4 * TWOD];

// ---------------- helpers ----------------
__device__ __forceinline__ uint32_t smem_u32(const void* p) {
    uint32_t a;
    asm("{ .reg .u64 t; cvta.to.shared.u64 t, %1; cvt.u32.u64 %0, t; }" : "=r"(a) : "l"(p));
    return a;
}
__device__ __forceinline__ void ldsm_x4(uint32_t* r, uint32_t addr) {
    asm volatile("ldmatrix.sync.aligned.m8n8.x4.shared.b16 {%0,%1,%2,%3}, [%4];"
        : "=r"(r[0]), "=r"(r[1]), "=r"(r[2]), "=r"(r[3]) : "r"(addr));
}
__device__ __forceinline__ void mma16816(float* d, const uint32_t* a, const uint32_t* b) {
    asm volatile(
        "mma.sync.aligned.m16n8k16.row.col.f32.bf16.bf16.f32 "
        "{%0,%1,%2,%3}, {%4,%5,%6,%7}, {%8,%9}, {%0,%1,%2,%3};"
        : "+f"(d[0]), "+f"(d[1]), "+f"(d[2]), "+f"(d[3])
        : "r"(a[0]), "r"(a[1]), "r"(a[2]), "r"(a[3]), "r"(b[0]), "r"(b[1]));
}
#define CP16(dst, src) asm volatile("cp.async.cg.shared.global [%0], [%1], 16;" :: "r"(dst), "l"(src))
#define CP_COMMIT()    asm volatile("cp.async.commit_group;" ::: "memory")
#define CP_WAIT(n)     asm volatile("cp.async.wait_group %0;" :: "n"(n) : "memory")

__device__ __forceinline__ float tanh_fast(float x) {
    float y;
    asm("tanh.approx.f32 %0, %1;" : "=f"(y) : "f"(x));
    return y;
}
__device__ __forceinline__ unsigned f2key(float f) {
    unsigned u = __float_as_uint(f);
    return (u & 0x80000000u) ? ~u : (u | 0x80000000u);
}
__device__ __forceinline__ float key2f(unsigned k) {
    unsigned u = (k & 0x80000000u) ? (k & 0x7FFFFFFFu) : ~k;
    return __uint_as_float(u);
}

// ---- 1024-thread block reductions (warp shuffle, two-level) ----
__device__ __forceinline__ float bsum1024(float v, float* sw) {
    int lane = threadIdx.x & 31, wid = threadIdx.x >> 5;
    #pragma unroll
    for (int o = 16; o; o >>= 1) v += __shfl_xor_sync(0xffffffffu, v, o);
    if (!lane) sw[wid] = v;
    __syncthreads();
    if (wid == 0) {
        float x = sw[lane];
        #pragma unroll
        for (int o = 16; o; o >>= 1) x += __shfl_xor_sync(0xffffffffu, x, o);
        if (!lane) sw[32] = x;
    }
    __syncthreads();
    float r = sw[32];
    __syncthreads();
    return r;
}
template<int NV>
__device__ __forceinline__ void bsumv(float* v, float* sw) {
    int lane = threadIdx.x & 31, wid = threadIdx.x >> 5;
    #pragma unroll
    for (int o = 16; o; o >>= 1)
        #pragma unroll
        for (int i = 0; i < NV; i++) v[i] += __shfl_xor_sync(0xffffffffu, v[i], o);
    if (!lane)
        #pragma unroll
        for (int i = 0; i < NV; i++) sw[i * 33 + wid] = v[i];
    __syncthreads();
    if (wid == 0) {
        float x[NV];
        #pragma unroll
        for (int i = 0; i < NV; i++) x[i] = sw[i * 33 + lane];
        #pragma unroll
        for (int o = 16; o; o >>= 1)
            #pragma unroll
            for (int i = 0; i < NV; i++) x[i] += __shfl_xor_sync(0xffffffffu, x[i], o);
        if (!lane)
            #pragma unroll
            for (int i = 0; i < NV; i++) sw[i * 33 + 32] = x[i];
    }
    __syncthreads();
    #pragma unroll
    for (int i = 0; i < NV; i++) v[i] = sw[i * 33 + 32];
    __syncthreads();
}
template<int NV>
__device__ __forceinline__ void bmaxv(float* v, float* sw) {
    int lane = threadIdx.x & 31, wid = threadIdx.x >> 5;
    #pragma unroll
    for (int o = 16; o; o >>= 1)
        #pragma unroll
        for (int i = 0; i < NV; i++) v[i] = fmaxf(v[i], __shfl_xor_sync(0xffffffffu, v[i], o));
    if (!lane)
        #pragma unroll
        for (int i = 0; i < NV; i++) sw[i * 33 + wid] = v[i];
    __syncthreads();
    if (wid == 0) {
        float x[NV];
        #pragma unroll
        for (int i = 0; i < NV; i++) x[i] = sw[i * 33 + lane];
        #pragma unroll
        for (int o = 16; o; o >>= 1)
            #pragma unroll
            for (int i = 0; i < NV; i++) x[i] = fmaxf(x[i], __shfl_xor_sync(0xffffffffu, x[i], o));
        if (!lane)
            #pragma unroll
            for (int i = 0; i < NV; i++) sw[i * 33 + 32] = x[i];
    }
    __syncthreads();
    #pragma unroll
    for (int i = 0; i < NV; i++) v[i] = sw[i * 33 + 32];
    __syncthreads();
}
__device__ __forceinline__ int bisum1024(int v, int* sw) {
    int lane = threadIdx.x & 31, wid = threadIdx.x >> 5;
    #pragma unroll
    for (int o = 16; o; o >>= 1) v += __shfl_xor_sync(0xffffffffu, v, o);
    if (!lane) sw[wid] = v;
    __syncthreads();
    if (wid == 0) {
        int x = sw[lane];
        #pragma unroll
        for (int o = 16; o; o >>= 1) x += __shfl_xor_sync(0xffffffffu, x, o);
        if (!lane) sw[32] = x;
    }
    __syncthreads();
    int r = sw[32];
    __syncthreads();
    return r;
}
__device__ __forceinline__ int bexscan1024(int v, int* sw) {
    int lane = threadIdx.x & 31, wid = threadIdx.x >> 5;
    int x = v;
    #pragma unroll
    for (int o = 1; o < 32; o <<= 1) {
        int y = __shfl_up_sync(0xffffffffu, x, o);
        if (lane >= o) x += y;
    }
    if (lane == 31) sw[wid] = x;
    __syncthreads();
    if (wid == 0) {
        int w = sw[lane], inc = w;
        #pragma unroll
        for (int o = 1; o < 32; o <<= 1) {
            int y = __shfl_up_sync(0xffffffffu, inc, o);
            if (lane >= o) inc += y;
        }
        sw[lane] = inc - w;
    }
    __syncthreads();
    int r = sw[wid] + x - v;
    __syncthreads();
    return r;
}
// 512-thread sum (fuse2 LN): 2 syncs instead of 10
__device__ __forceinline__ float bsum512(float v, float* sw) {
    int lane = threadIdx.x & 31, wid = threadIdx.x >> 5;   // 16 warps
    #pragma unroll
    for (int o = 16; o; o >>= 1) v += __shfl_xor_sync(0xffffffffu, v, o);
    if (!lane) sw[wid] = v;
    __syncthreads();
    if (wid == 0) {
        float x = (lane < 16) ? sw[lane] : 0.f;
        #pragma unroll
        for (int o = 8; o; o >>= 1) x += __shfl_xor_sync(0xffffffffu, x, o);
        if (!lane) sw[16] = x;
    }
    __syncthreads();
    float r = sw[16];
    __syncthreads();
    return r;
}

// exact K-th largest among 2048 keys; 1024 threads, 2 keys each.
__device__ unsigned radix1024(const unsigned* keys, int K,
                              unsigned* hist, volatile unsigned* bc) {
    const int t = threadIdx.x;
    const int n0 = t * 2;
    unsigned prefix = 0;
    int rem = K;
    for (int pass = 0; pass < 4; pass++) {
        const int shift = 24 - 8 * pass;
        const unsigned hm = pass ? (0xFFFFFFFFu << (shift + 8)) : 0u;
        if (t < 256) hist[t] = 0;
        __syncthreads();
        #pragma unroll
        for (int q = 0; q < 2; q++) {
            unsigned u = keys[n0 + q];
            if ((u & hm) == prefix) atomicAdd(&hist[(u >> shift) & 255u], 1u);
        }
        __syncthreads();
        if (t < 32) {
            int base = t * 8;
            int v[8], s = 0;
            #pragma unroll
            for (int i = 0; i < 8; i++) { v[i] = (int)hist[255 - (base + i)]; s += v[i]; }
            int inc = s;
            #pragma unroll
            for (int o = 1; o < 32; o <<= 1) {
                int y = __shfl_up_sync(0xffffffffu, inc, o);
                if (t >= o) inc += y;
            }
            int run = inc - s;
            #pragma unroll
            for (int i = 0; i < 8; i++) {
                int prev = run;
                run += v[i];
                if (run >= rem && prev < rem) {
                    bc[0] = prefix | ((unsigned)(255 - (base + i)) << shift);
                    bc[1] = (unsigned)(rem - prev);
                }
            }
        }
        __syncthreads();
        prefix = bc[0];
        rem = (int)bc[1];
        __syncthreads();
    }
    return prefix;
}

// ---------------- K0: weight image + scalars ----------------
__global__ void k_prep(const float* __restrict__ Ws1, const float* __restrict__ Wa1,
                       const float* __restrict__ bs1, const float* __restrict__ Ws2,
                       const float* __restrict__ bs2, const float* __restrict__ ba1,
                       const float* __restrict__ Wa2, const float* __restrict__ ba2) {
    if (blockIdx.x == 320) {
        int t = threadIdx.x;
        int g = t >> 6, ch = t & 63;
        g_b1c[t] = (g == 0) ? bs1[ch] : ba1[(g - 1) * Hc + ch];
        g_w2c[t] = (g == 0) ? Ws2[ch] : Wa2[(g - 1) * Hc + ch];
        if (t < 4) g_b2c[t] = (t == 0) ? bs2[0] : ba2[t - 1];
        return;
    }
    int gid = blockIdx.x * 256 + threadIdx.x;   // < 81920
    int k = gid & 31;
    int row = (gid >> 5) % 320;
    int c = gid / 10240;                        // chunk
    int kg = c * 32 + k;
    float w;
    bool resid = (row >= 256);
    int n = resid ? (row - 256) : row;
    if (n < 64) w = Ws1[kg * 64 + n];
    else {
        int br = (n - 64) >> 6, h = (n - 64) & 63;
        w = Wa1[(br * 256 + kg) * 64 + h];
    }
    __nv_bfloat16 h1 = __float2bfloat16(w);
    __nv_bfloat16 v = resid ? __float2bfloat16(w - __bfloat162float(h1)) : h1;
    g_B[gid] = v;
}

// ---------------- K1: split-bf16 HMMA scorer GEMM (exact R11 2-CTA form) ----------------
__global__ void __launch_bounds__(256, 2) k_gemm_mma(const float* __restrict__ X) {
    extern __shared__ char sm[];
    const int tid = threadIdx.x;
    const int lane = tid & 31;
    const int wid = tid >> 5;
    const int wm = wid & 3;
    const int wn = wid >> 2;
    const int m0g = blockIdx.y * 128;
    const int ct = blockIdx.x;
    const uint32_t sb = smem_u32(sm);
    float* sb1 = (float*)(sm + SB_SCAL);
    float* sw2 = sb1 + 256;

    sb1[tid] = g_b1c[tid];
    sw2[tid] = g_w2c[tid];

    float acc[2][8][4];
    #pragma unroll
    for (int i = 0; i < 2; i++)
        #pragma unroll
        for (int j = 0; j < 8; j++)
            #pragma unroll
            for (int e = 0; e < 4; e++) acc[i][j][e] = 0.f;

    const char* gB = (const char*)g_B;
    const bool heavy = (ct == 0) && (wn == 0);

    auto stage_B = [&](int c, int buf) {
        uint32_t dbase = sb + buf * B_BUF_B;
        #pragma unroll
        for (int i = 0; i < 2; i++) {
            int flat = tid + i * 256;
            int u = flat & 3;
            int n = flat >> 2;
            uint32_t dst = dbase + n * 80 + u * 16;
            const char* src = gB + (size_t)((c * 320 + ct * 128 + n) * 64 + u * 16);
            CP16(dst, src);
        }
        if (ct == 0) {
            int u = tid & 3;
            int n = tid >> 2;
            uint32_t dst = dbase + (128 + n) * 80 + u * 16;
            const char* src = gB + (size_t)((c * 320 + 256 + n) * 64 + u * 16);
            CP16(dst, src);
        }
    };

    float4 av[4];
    auto load_x = [&](int c) {
        #pragma unroll
        for (int q = 0; q < 4; q++) {
            int row = q * 32 + (tid >> 3);
            int col = (tid & 7) * 4 + c * 32;
            av[q] = *(const float4*)(X + (size_t)(m0g + row) * 256 + col);
        }
    };
    auto convert_a = [&]() {
        #pragma unroll
        for (int q = 0; q < 4; q++) {
            int row = q * 32 + (tid >> 3);
            uint32_t off = row * 80 + (tid & 7) * 8;
            float v[4] = {av[q].x, av[q].y, av[q].z, av[q].w};
            unsigned short s1[4], s2[4];
            #pragma unroll
            for (int e = 0; e < 4; e++) {
                __nv_bfloat16 h1 = __float2bfloat16(v[e]);
                __nv_bfloat16 h2 = __float2bfloat16(v[e] - __bfloat162float(h1));
                s1[e] = __bfloat16_as_ushort(h1);
                s2[e] = __bfloat16_as_ushort(h2);
            }
            *(uint2*)(sm + SB_A + off) =
                make_uint2((unsigned)s1[0] | ((unsigned)s1[1] << 16),
                           (unsigned)s1[2] | ((unsigned)s1[3] << 16));
            if (ct == 0)
                *(uint2*)(sm + SB_A + A_LIMB_B + off) =
                    make_uint2((unsigned)s2[0] | ((unsigned)s2[1] << 16),
                               (unsigned)s2[2] | ((unsigned)s2[3] << 16));
        }
    };

    stage_B(0, 0); CP_COMMIT();
    load_x(0);

    for (int c = 0; c < 8; c++) {
        if (c < 7) { stage_B(c + 1, (c + 1) & 1); CP_COMMIT(); }
        convert_a();
        if (c < 7) load_x(c + 1);
        if (c < 7) { CP_WAIT(1); } else { CP_WAIT(0); }
        __syncthreads();

        uint32_t bbuf = sb + (c & 1) * B_BUF_B;
        #pragma unroll
        for (int ks = 0; ks < 2; ks++) {
            uint32_t acol = ks * 32 + ((lane >> 4) & 1) * 16;
            uint32_t arow = (wm * 32 + (lane & 15)) * 80;
            uint32_t arow2 = (wm * 32 + 16 + (lane & 15)) * 80;
            uint32_t a1r0[4], a1r1[4], a2r0[4], a2r1[4];
            ldsm_x4(a1r0, sb + SB_A + arow + acol);
            ldsm_x4(a1r1, sb + SB_A + arow2 + acol);
            if (heavy) {
                ldsm_x4(a2r0, sb + SB_A + A_LIMB_B + arow + acol);
                ldsm_x4(a2r1, sb + SB_A + A_LIMB_B + arow2 + acol);
            }
            const uint32_t koff = ks * 32 + ((lane >> 3) & 1) * 16;
            #pragma unroll
            for (int jj = 0; jj < 4; jj++) {
                uint32_t bfr[4];
                int rowb = wn * 64 + jj * 16 + ((lane >> 4) & 1) * 8 + (lane & 7);
                ldsm_x4(bfr, bbuf + rowb * 80 + koff);
                mma16816(acc[0][jj * 2],     a1r0, bfr);
                mma16816(acc[1][jj * 2],     a1r1, bfr);
                mma16816(acc[0][jj * 2 + 1], a1r0, bfr + 2);
                mma16816(acc[1][jj * 2 + 1], a1r1, bfr + 2);
                if (heavy) {
                    mma16816(acc[0][jj * 2],     a2r0, bfr);
                    mma16816(acc[1][jj * 2],     a2r1, bfr);
                    mma16816(acc[0][jj * 2 + 1], a2r0, bfr + 2);
                    mma16816(acc[1][jj * 2 + 1], a2r1, bfr + 2);
                    uint32_t bfr2[4];
                    int rowb2 = 128 + jj * 16 + ((lane >> 4) & 1) * 8 + (lane & 7);
                    ldsm_x4(bfr2, bbuf + rowb2 * 80 + koff);
                    mma16816(acc[0][jj * 2],     a1r0, bfr2);
                    mma16816(acc[1][jj * 2],     a1r1, bfr2);
                    mma16816(acc[0][jj * 2 + 1], a1r0, bfr2 + 2);
                    mma16816(acc[1][jj * 2 + 1], a1r1, bfr2 + 2);
                }
            }
        }
        __syncthreads();
    }

    const int g = ct * 2 + wn;
    const bool is_relu = (g == 0);
    const int cbase = ct * 128 + wn * 64;
    const float b2 = g_b2c[g];

    #pragma unroll
    for (int mf = 0; mf < 2; mf++) {
        float p0 = 0.f, p1 = 0.f;
        #pragma unroll
        for (int j = 0; j < 8; j++) {
            int c0 = cbase + j * 8 + (lane & 3) * 2;
            float v0 = acc[mf][j][0] + sb1[c0];
            float v1 = acc[mf][j][1] + sb1[c0 + 1];
            float v2 = acc[mf][j][2] + sb1[c0];
            float v3 = acc[mf][j][3] + sb1[c0 + 1];
            float f0 = is_relu ? fmaxf(v0, 0.f) : tanh_fast(v0);
            float f1 = is_relu ? fmaxf(v1, 0.f) : tanh_fast(v1);
            float f2 = is_relu ? fmaxf(v2, 0.f) : tanh_fast(v2);
            float f3 = is_relu ? fmaxf(v3, 0.f) : tanh_fast(v3);
            p0 = fmaf(f0, sw2[c0], p0);
            p0 = fmaf(f1, sw2[c0 + 1], p0);
            p1 = fmaf(f2, sw2[c0], p1);
            p1 = fmaf(f3, sw2[c0 + 1], p1);
        }
        p0 += __shfl_xor_sync(0xffffffff, p0, 1);
        p0 += __shfl_xor_sync(0xffffffff, p0, 2);
        p1 += __shfl_xor_sync(0xffffffff, p1, 1);
        p1 += __shfl_xor_sync(0xffffffff, p1, 2);
        if ((lane & 3) == 0) {
            int m = m0g + wm * 32 + mf * 16 + (lane >> 2);
            g_scores[(size_t)g * Mc + m]     = p0 + b2;
            g_scores[(size_t)g * Mc + m + 8] = p1 + b2;
        }
    }
}

// ---------------- K2: per-batch top-k, softmax, diagnostics (1024 thr) ----------------
__global__ void __launch_bounds__(1024) k_perbatch(const float* __restrict__ mask,
                                                   float* __restrict__ out) {
    const int b = blockIdx.x;
    const int t = threadIdx.x;
    const int n0 = t * 2;

    __shared__ unsigned s_key[2048];
    __shared__ unsigned s_hist[256];
    __shared__ float    s_wf[3 * 33];
    __shared__ int      s_wi[33];
    __shared__ unsigned s_bc[2];

    float mk[2];
    mk[0] = mask[b * Nc + n0];
    mk[1] = mask[b * Nc + n0 + 1];

    float cnt = bsum1024(mk[0] + mk[1], s_wf);
    float inv_mean = 1.f / fmaxf(cnt, 1.f);

    #pragma unroll
    for (int q = 0; q < 2; q++) {
        float sc = g_scores[(size_t)b * Nc + n0 + q];
        if (mk[q] == 0.f) sc = NEG_INF_F;
        s_key[n0 + q] = f2key(sc);
    }
    __syncthreads();

    unsigned T = radix1024(s_key, KTOP, s_hist, s_bc);

    int lg = 0, le = 0;
    unsigned uk[2];
    #pragma unroll
    for (int q = 0; q < 2; q++) {
        uk[q] = s_key[n0 + q];
        lg += (uk[q] > T);
        le += (uk[q] == T);
    }
    int cg = bisum1024(lg, s_wi);
    int need = KTOP - cg;
    int excl = bexscan1024(le, s_wi);

    float tmv[2];
    float lc = 0.f;
    int rank = excl;
    #pragma unroll
    for (int q = 0; q < 2; q++) {
        float tmq = 0.f;
        if (uk[q] > T) tmq = 1.f;
        else if (uk[q] == T) { if (rank < need) tmq = 1.f; rank++; }
        tmv[q] = tmq;
        out[OUT_TOPK + b * Nc + n0 + q] = tmq;
        lc += tmq * mk[q];
    }
    float csum = bsum1024(lc, s_wf);
    float invden = 1.f / fmaxf(csum, 1.f);
    #pragma unroll
    for (int q = 0; q < 2; q++) {
        g_poolw[((size_t)b * 5 + 0) * Nc + n0 + q] = mk[q] * inv_mean;
        g_poolw[((size_t)b * 5 + 1) * Nc + n0 + q] = tmv[q] * mk[q] * invden;
    }

    float sc3[3][2];
    float lm[3] = {-3e38f, -3e38f, -3e38f};
    #pragma unroll
    for (int k = 0; k < 3; k++)
        #pragma unroll
        for (int q = 0; q < 2; q++) {
            float s = g_scores[(size_t)(1 + k) * Mc + b * Nc + n0 + q];
            if (mk[q] == 0.f) s = NEG_INF_F;
            sc3[k][q] = s;
            lm[k] = fmaxf(lm[k], s);
        }
    bmaxv<3>(lm, s_wf);
    float ls[3] = {0.f, 0.f, 0.f};
    #pragma unroll
    for (int k = 0; k < 3; k++)
        #pragma unroll
        for (int q = 0; q < 2; q++) {
            sc3[k][q] = expf(sc3[k][q] - lm[k]);
            ls[k] += sc3[k][q];
        }
    bsumv<3>(ls, s_wf);

    float avq[2] = {0.f, 0.f};
    #pragma unroll
    for (int k = 0; k < 3; k++) {
        float inv = 1.f / ls[k];
        #pragma unroll
        for (int q = 0; q < 2; q++) {
            float a = (mk[q] == 0.f) ? 0.f : sc3[k][q] * inv;
            out[OUT_ALLA + ((size_t)b * NBc + k) * Nc + n0 + q] = a;
            g_poolw[((size_t)b * 5 + 2 + k) * Nc + n0 + q] = a;
            avq[q] += a;
        }
    }
    #pragma unroll
    for (int q = 0; q < 2; q++) avq[q] *= (1.f / 3.f);

    float es[2] = {0.f, 0.f};
    #pragma unroll
    for (int q = 0; q < 2; q++) {
        out[OUT_AVG + b * Nc + n0 + q] = avq[q];
        es[0] += avq[q] * logf(avq[q] + 1e-8f);
        es[1] += avq[q] * avq[q];
        s_key[n0 + q] = f2key(avq[q]);
    }
    bsumv<2>(es, s_wf);   // also fences s_key writes
    if (t == 0) {
        out[OUT_ENT + b] = -es[0];
        out[OUT_EFF + b] = 1.f / es[1];
    }
    __syncthreads();

    unsigned T5 = radix1024(s_key, K5, s_hist, s_bc);
    int lg5 = 0;
    float lsum5 = 0.f;
    #pragma unroll
    for (int q = 0; q < 2; q++) {
        unsigned u = s_key[n0 + q];
        if (u > T5) { lg5++; lsum5 += avq[q]; }
    }
    int cg5 = bisum1024(lg5, s_wi);
    float sgt = bsum1024(lsum5, s_wf);
    if (t == 0)
        out[OUT_T5 + b] = sgt + (float)(K5 - cg5) * key2f(T5);
}

// ---------------- K3: pooling (exact R8/R11 version) ----------------
__global__ void __launch_bounds__(256) k_pool2(const float* __restrict__ X) {
    const int b = blockIdx.x >> 3;
    const int seg = blockIdx.x & 7;
    const int tid = threadIdx.x;
    const int tx = tid & 63;
    const int rg = tid >> 6;
    __shared__ float sw[5][256];
    __shared__ float part[4][5][256];

    #pragma unroll
    for (int p = 0; p < 5; p++)
        sw[p][tid] = g_poolw[((size_t)b * 5 + p) * Nc + seg * 256 + tid];
    __syncthreads();

    const float* xb = X + ((size_t)(b * Nc + seg * 256 + rg * 64)) * Dc + tx * 4;
    float4 a0 = {0,0,0,0}, a1 = {0,0,0,0}, a2 = {0,0,0,0}, a3 = {0,0,0,0}, a4 = {0,0,0,0};
    #pragma unroll 4
    for (int n = 0; n < 64; n++) {
        float4 xv = *(const float4*)(xb + (size_t)n * Dc);
        float w0 = sw[0][rg * 64 + n], w1 = sw[1][rg * 64 + n], w2 = sw[2][rg * 64 + n];
        float w3 = sw[3][rg * 64 + n], w4 = sw[4][rg * 64 + n];
        a0.x = fmaf(xv.x, w0, a0.x); a0.y = fmaf(xv.y, w0, a0.y);
        a0.z = fmaf(xv.z, w0, a0.z); a0.w = fmaf(xv.w, w0, a0.w);
        a1.x = fmaf(xv.x, w1, a1.x); a1.y = fmaf(xv.y, w1, a1.y);
        a1.z = fmaf(xv.z, w1, a1.z); a1.w = fmaf(xv.w, w1, a1.w);
        a2.x = fmaf(xv.x, w2, a2.x); a2.y = fmaf(xv.y, w2, a2.y);
        a2.z = fmaf(xv.z, w2, a2.z); a2.w = fmaf(xv.w, w2, a2.w);
        a3.x = fmaf(xv.x, w3, a3.x); a3.y = fmaf(xv.y, w3, a3.y);
        a3.z = fmaf(xv.z, w3, a3.z); a3.w = fmaf(xv.w, w3, a3.w);
        a4.x = fmaf(xv.x, w4, a4.x); a4.y = fmaf(xv.y, w4, a4.y);
        a4.z = fmaf(xv.z, w4, a4.z); a4.w = fmaf(xv.w, w4, a4.w);
    }
    *(float4*)&part[rg][0][tx * 4] = a0;
    *(float4*)&part[rg][1][tx * 4] = a1;
    *(float4*)&part[rg][2][tx * 4] = a2;
    *(float4*)&part[rg][3][tx * 4] = a3;
    *(float4*)&part[rg][4][tx * 4] = a4;
    __syncthreads();

    float* dst = g_poolpart + ((size_t)(b * NSEG + seg)) * 1280;
    #pragma unroll
    for (int p = 0; p < 5; p++) {
        float s = part[0][p][tid] + part[1][p][tid] + part[2][p][tid] + part[3][p][tid];
        dst[p * 256 + tid] = s;
    }
}

// ---------------- K4a: fusion GEMV1 partials (exact R11: 2 rows/block, 128 blocks) ----------------
__global__ void __launch_bounds__(512) k_fuse1(const float* __restrict__ Wf1) {
    const int bp = blockIdx.x >> 2;
    const int seg = blockIdx.x & 3;
    const int c = threadIdx.x;
    const int b0 = bp * 2, b1 = b0 + 1;
    __shared__ float sc0[320];
    __shared__ float sc1[320];

    for (int i = c; i < 320; i += 512) {
        int gi = seg * 320 + i;
        float s0 = 0.f, s1 = 0.f;
        #pragma unroll
        for (int se = 0; se < NSEG; se++) {
            s0 += g_poolpart[((size_t)(b0 * NSEG + se)) * 1280 + gi];
            s1 += g_poolpart[((size_t)(b1 * NSEG + se)) * 1280 + gi];
        }
        sc0[i] = s0;
        sc1[i] = s1;
    }
    __syncthreads();

    float acc0 = 0.f, acc1 = 0.f;
    const float* W = Wf1 + (size_t)(seg * 320) * TWOD + c;
    #pragma unroll 8
    for (int j = 0; j < 320; j++) {
        float w = W[(size_t)j * TWOD];
        acc0 = fmaf(sc0[j], w, acc0);
        acc1 = fmaf(sc1[j], w, acc1);
    }
    g_fpart[(b0 * 4 + seg) * TWOD + c] = acc0;
    g_fpart[(b1 * 4 + seg) * TWOD + c] = acc1;
}

// ---------------- K4b: reduce + LN(shuffle) + GELU + GEMV2 (2 rows/block) ----------------
__global__ void __launch_bounds__(512) k_fuse2(const float* __restrict__ bf1,
                                               const float* __restrict__ lng,
                                               const float* __restrict__ lnb,
                                               const float* __restrict__ Wf2,
                                               const float* __restrict__ bf2,
                                               float* __restrict__ out) {
    const int bp = blockIdx.x;
    const int c = threadIdx.x;
    const int b0 = bp * 2, b1 = b0 + 1;
    __shared__ float sx0[TWOD];
    __shared__ float sx1[TWOD];
    __shared__ float red[17];

    float bb = bf1[c];
    float acc0 = bb, acc1 = bb;
    #pragma unroll
    for (int seg = 0; seg < 4; seg++) {
        acc0 += g_fpart[(b0 * 4 + seg) * TWOD + c];
        acc1 += g_fpart[(b1 * 4 + seg) * TWOD + c];
    }

    float gln = lng[c], bln = lnb[c];

    float mu0 = bsum512(acc0, red) * (1.f / TWOD);
    float dv0 = acc0 - mu0;
    float var0 = bsum512(dv0 * dv0, red) * (1.f / TWOD);
    float x0 = dv0 * rsqrtf(var0 + 1e-5f) * gln + bln;
    sx0[c] = 0.5f * x0 * (1.f + erff(x0 * 0.70710678118654752f));

    float mu1 = bsum512(acc1, red) * (1.f / TWOD);
    float dv1 = acc1 - mu1;
    float var1 = bsum512(dv1 * dv1, red) * (1.f / TWOD);
    float x1 = dv1 * rsqrtf(var1 + 1e-5f) * gln + bln;
    sx1[c] = 0.5f * x1 * (1.f + erff(x1 * 0.70710678118654752f));
    __syncthreads();

    float o0 = bf2[c], o1 = o0;
    #pragma unroll 8
    for (int j = 0; j < TWOD; j++) {
        float w = Wf2[(size_t)j * TWOD + c];
        o0 = fmaf(sx0[j], w, o0);
        o1 = fmaf(sx1[j], w, o1);
    }
    out[OUT_BAG + b0 * TWOD + c] = o0;
    out[OUT_BAG + b1 * TWOD + c] = o1;
}

// ---------------- launch ----------------
extern "C" void kernel_launch(void* const* d_in, const int* in_sizes, int n_in,
                              void* d_out, int out_size) {
    const float* inst = (const float*)d_in[0];
    const float* mask = (const float*)d_in[1];
    const float* Ws1 = (const float*)d_in[2];
    const float* bs1 = (const float*)d_in[3];
    const float* Ws2 = (const float*)d_in[4];
    const float* bs2 = (const float*)d_in[5];
    const float* Wa1 = (const float*)d_in[6];
    const float* ba1 = (const float*)d_in[7];
    const float* Wa2 = (const float*)d_in[8];
    const float* ba2 = (const float*)d_in[9];
    const float* Wf1 = (const float*)d_in[10];
    const float* bf1 = (const float*)d_in[11];
    const float* lng = (const float*)d_in[12];
    const float* lnb = (const float*)d_in[13];
    const float* Wf2 = (const float*)d_in[14];
    const float* bf2 = (const float*)d_in[15];
    float* out = (float*)d_out;

    static bool attr_done = false;
    if (!attr_done) {
        cudaFuncSetAttribute(k_gemm_mma, cudaFuncAttributeMaxDynamicSharedMemorySize, SMEM_DYN);
        attr_done = true;
    }

    k_prep<<<321, 256>>>(Ws1, Wa1, bs1, Ws2, bs2, ba1, Wa2, ba2);
    k_gemm_mma<<<dim3(2, Mc / 128), 256, SMEM_DYN>>>(inst);
    k_perbatch<<<Bc, 1024>>>(mask, out);
    k_pool2<<<Bc * NSEG, 256>>>(inst);
    k_fuse1<<<(Bc / 2) * 4, 512>>>(Wf1);
    k_fuse2<<<Bc / 2, 512>>>(bf1, lng, lnb, Wf2, bf2, out);
}

// round 16
// speedup vs baseline: 1.0779x; 1.0051x over previous
#include <cuda_runtime.h>
#include <cuda_bf16.h>
#include <math.h>
#include <stdint.h>

#define Bc   64
#define Nc   2048
#define Dc   256
#define Hc   64
#define NBc  3
#define Mc   (Bc * Nc)
#define KTOP 204
#define K5   102
#define TWOD 512
#define CATD 1280
#define NEG_INF_F (-1e30f)

#define OUT_BAG   0
#define OUT_ALLA  (OUT_BAG  + Bc * TWOD)
#define OUT_AVG   (OUT_ALLA + Bc * NBc * Nc)
#define OUT_TOPK  (OUT_AVG  + Bc * Nc)
#define OUT_ENT   (OUT_TOPK + Bc * Nc)
#define OUT_EFF   (OUT_ENT  + Bc)
#define OUT_T5    (OUT_EFF  + Bc)

// ---- GEMM smem layout (R11 2-CTA form) ----
#define B_BUF_B    15360
#define A_LIMB_B   10240
#define SB_A       30720
#define SB_SCAL    51200
#define SMEM_DYN   (51200 + 2048)
#define NSEG       8

// ---------------- device scratch ----------------
__device__ __nv_bfloat16 g_B[8 * 320 * 32];   // [chunk][row: 256 b1 + 64 b2scorer][k]
__device__ float g_b1c[256];
__device__ float g_w2c[256];
__device__ float g_b2c[4];
__device__ float g_scores[4L * Mc];           // [group][m]
__device__ float g_poolw[(long)Bc * 5 * Nc];
__device__ float g_poolpart[Bc * NSEG * 5 * 256];
__device__ float g_fpart[Bc * 4 * TWOD];

// ---------------- helpers ----------------
__device__ __forceinline__ uint32_t smem_u32(const void* p) {
    uint32_t a;
    asm("{ .reg .u64 t; cvta.to.shared.u64 t, %1; cvt.u32.u64 %0, t; }" : "=r"(a) : "l"(p));
    return a;
}
__device__ __forceinline__ void ldsm_x4(uint32_t* r, uint32_t addr) {
    asm volatile("ldmatrix.sync.aligned.m8n8.x4.shared.b16 {%0,%1,%2,%3}, [%4];"
        : "=r"(r[0]), "=r"(r[1]), "=r"(r[2]), "=r"(r[3]) : "r"(addr));
}
__device__ __forceinline__ void mma16816(float* d, const uint32_t* a, const uint32_t* b) {
    asm volatile(
        "mma.sync.aligned.m16n8k16.row.col.f32.bf16.bf16.f32 "
        "{%0,%1,%2,%3}, {%4,%5,%6,%7}, {%8,%9}, {%0,%1,%2,%3};"
        : "+f"(d[0]), "+f"(d[1]), "+f"(d[2]), "+f"(d[3])
        : "r"(a[0]), "r"(a[1]), "r"(a[2]), "r"(a[3]), "r"(b[0]), "r"(b[1]));
}
#define CP16(dst, src) asm volatile("cp.async.cg.shared.global [%0], [%1], 16;" :: "r"(dst), "l"(src))
#define CP_COMMIT()    asm volatile("cp.async.commit_group;" ::: "memory")
#define CP_WAIT(n)     asm volatile("cp.async.wait_group %0;" :: "n"(n) : "memory")

__device__ __forceinline__ float tanh_fast(float x) {
    float y;
    asm("tanh.approx.f32 %0, %1;" : "=f"(y) : "f"(x));
    return y;
}
__device__ __forceinline__ unsigned f2key(float f) {
    unsigned u = __float_as_uint(f);
    return (u & 0x80000000u) ? ~u : (u | 0x80000000u);
}
__device__ __forceinline__ float key2f(unsigned k) {
    unsigned u = (k & 0x80000000u) ? (k & 0x7FFFFFFFu) : ~k;
    return __uint_as_float(u);
}

// ---- 1024-thread block reductions (warp shuffle, two-level) ----
__device__ __forceinline__ float bsum1024(float v, float* sw) {
    int lane = threadIdx.x & 31, wid = threadIdx.x >> 5;
    #pragma unroll
    for (int o = 16; o; o >>= 1) v += __shfl_xor_sync(0xffffffffu, v, o);
    if (!lane) sw[wid] = v;
    __syncthreads();
    if (wid == 0) {
        float x = sw[lane];
        #pragma unroll
        for (int o = 16; o; o >>= 1) x += __shfl_xor_sync(0xffffffffu, x, o);
        if (!lane) sw[32] = x;
    }
    __syncthreads();
    float r = sw[32];
    __syncthreads();
    return r;
}
template<int NV>
__device__ __forceinline__ void bsumv(float* v, float* sw) {
    int lane = threadIdx.x & 31, wid = threadIdx.x >> 5;
    #pragma unroll
    for (int o = 16; o; o >>= 1)
        #pragma unroll
        for (int i = 0; i < NV; i++) v[i] += __shfl_xor_sync(0xffffffffu, v[i], o);
    if (!lane)
        #pragma unroll
        for (int i = 0; i < NV; i++) sw[i * 33 + wid] = v[i];
    __syncthreads();
    if (wid == 0) {
        float x[NV];
        #pragma unroll
        for (int i = 0; i < NV; i++) x[i] = sw[i * 33 + lane];
        #pragma unroll
        for (int o = 16; o; o >>= 1)
            #pragma unroll
            for (int i = 0; i < NV; i++) x[i] += __shfl_xor_sync(0xffffffffu, x[i], o);
        if (!lane)
            #pragma unroll
            for (int i = 0; i < NV; i++) sw[i * 33 + 32] = x[i];
    }
    __syncthreads();
    #pragma unroll
    for (int i = 0; i < NV; i++) v[i] = sw[i * 33 + 32];
    __syncthreads();
}
template<int NV>
__device__ __forceinline__ void bmaxv(float* v, float* sw) {
    int lane = threadIdx.x & 31, wid = threadIdx.x >> 5;
    #pragma unroll
    for (int o = 16; o; o >>= 1)
        #pragma unroll
        for (int i = 0; i < NV; i++) v[i] = fmaxf(v[i], __shfl_xor_sync(0xffffffffu, v[i], o));
    if (!lane)
        #pragma unroll
        for (int i = 0; i < NV; i++) sw[i * 33 + wid] = v[i];
    __syncthreads();
    if (wid == 0) {
        float x[NV];
        #pragma unroll
        for (int i = 0; i < NV; i++) x[i] = sw[i * 33 + lane];
        #pragma unroll
        for (int o = 16; o; o >>= 1)
            #pragma unroll
            for (int i = 0; i < NV; i++) x[i] = fmaxf(x[i], __shfl_xor_sync(0xffffffffu, x[i], o));
        if (!lane)
            #pragma unroll
            for (int i = 0; i < NV; i++) sw[i * 33 + 32] = x[i];
    }
    __syncthreads();
    #pragma unroll
    for (int i = 0; i < NV; i++) v[i] = sw[i * 33 + 32];
    __syncthreads();
}
__device__ __forceinline__ int bisum1024(int v, int* sw) {
    int lane = threadIdx.x & 31, wid = threadIdx.x >> 5;
    #pragma unroll
    for (int o = 16; o; o >>= 1) v += __shfl_xor_sync(0xffffffffu, v, o);
    if (!lane) sw[wid] = v;
    __syncthreads();
    if (wid == 0) {
        int x = sw[lane];
        #pragma unroll
        for (int o = 16; o; o >>= 1) x += __shfl_xor_sync(0xffffffffu, x, o);
        if (!lane) sw[32] = x;
    }
    __syncthreads();
    int r = sw[32];
    __syncthreads();
    return r;
}
__device__ __forceinline__ int bexscan1024(int v, int* sw) {
    int lane = threadIdx.x & 31, wid = threadIdx.x >> 5;
    int x = v;
    #pragma unroll
    for (int o = 1; o < 32; o <<= 1) {
        int y = __shfl_up_sync(0xffffffffu, x, o);
        if (lane >= o) x += y;
    }
    if (lane == 31) sw[wid] = x;
    __syncthreads();
    if (wid == 0) {
        int w = sw[lane], inc = w;
        #pragma unroll
        for (int o = 1; o < 32; o <<= 1) {
            int y = __shfl_up_sync(0xffffffffu, inc, o);
            if (lane >= o) inc += y;
        }
        sw[lane] = inc - w;
    }
    __syncthreads();
    int r = sw[wid] + x - v;
    __syncthreads();
    return r;
}

// exact K-th largest among 2048 keys; 1024 threads, 2 keys each.
__device__ unsigned radix1024(const unsigned* keys, int K,
                              unsigned* hist, volatile unsigned* bc) {
    const int t = threadIdx.x;
    const int n0 = t * 2;
    unsigned prefix = 0;
    int rem = K;
    for (int pass = 0; pass < 4; pass++) {
        const int shift = 24 - 8 * pass;
        const unsigned hm = pass ? (0xFFFFFFFFu << (shift + 8)) : 0u;
        if (t < 256) hist[t] = 0;
        __syncthreads();
        #pragma unroll
        for (int q = 0; q < 2; q++) {
            unsigned u = keys[n0 + q];
            if ((u & hm) == prefix) atomicAdd(&hist[(u >> shift) & 255u], 1u);
        }
        __syncthreads();
        if (t < 32) {
            int base = t * 8;
            int v[8], s = 0;
            #pragma unroll
            for (int i = 0; i < 8; i++) { v[i] = (int)hist[255 - (base + i)]; s += v[i]; }
            int inc = s;
            #pragma unroll
            for (int o = 1; o < 32; o <<= 1) {
                int y = __shfl_up_sync(0xffffffffu, inc, o);
                if (t >= o) inc += y;
            }
            int run = inc - s;
            #pragma unroll
            for (int i = 0; i < 8; i++) {
                int prev = run;
                run += v[i];
                if (run >= rem && prev < rem) {
                    bc[0] = prefix | ((unsigned)(255 - (base + i)) << shift);
                    bc[1] = (unsigned)(rem - prev);
                }
            }
        }
        __syncthreads();
        prefix = bc[0];
        rem = (int)bc[1];
        __syncthreads();
    }
    return prefix;
}

// ---------------- K0: weight image + scalars ----------------
__global__ void k_prep(const float* __restrict__ Ws1, const float* __restrict__ Wa1,
                       const float* __restrict__ bs1, const float* __restrict__ Ws2,
                       const float* __restrict__ bs2, const float* __restrict__ ba1,
                       const float* __restrict__ Wa2, const float* __restrict__ ba2) {
    if (blockIdx.x == 320) {
        int t = threadIdx.x;
        int g = t >> 6, ch = t & 63;
        g_b1c[t] = (g == 0) ? bs1[ch] : ba1[(g - 1) * Hc + ch];
        g_w2c[t] = (g == 0) ? Ws2[ch] : Wa2[(g - 1) * Hc + ch];
        if (t < 4) g_b2c[t] = (t == 0) ? bs2[0] : ba2[t - 1];
        return;
    }
    int gid = blockIdx.x * 256 + threadIdx.x;   // < 81920
    int k = gid & 31;
    int row = (gid >> 5) % 320;
    int c = gid / 10240;                        // chunk
    int kg = c * 32 + k;
    float w;
    bool resid = (row >= 256);
    int n = resid ? (row - 256) : row;
    if (n < 64) w = Ws1[kg * 64 + n];
    else {
        int br = (n - 64) >> 6, h = (n - 64) & 63;
        w = Wa1[(br * 256 + kg) * 64 + h];
    }
    __nv_bfloat16 h1 = __float2bfloat16(w);
    __nv_bfloat16 v = resid ? __float2bfloat16(w - __bfloat162float(h1)) : h1;
    g_B[gid] = v;
}

// ---------------- K1: split-bf16 HMMA scorer GEMM (exact R11 2-CTA form) ----------------
__global__ void __launch_bounds__(256, 2) k_gemm_mma(const float* __restrict__ X) {
    extern __shared__ char sm[];
    const int tid = threadIdx.x;
    const int lane = tid & 31;
    const int wid = tid >> 5;
    const int wm = wid & 3;
    const int wn = wid >> 2;
    const int m0g = blockIdx.y * 128;
    const int ct = blockIdx.x;
    const uint32_t sb = smem_u32(sm);
    float* sb1 = (float*)(sm + SB_SCAL);
    float* sw2 = sb1 + 256;

    sb1[tid] = g_b1c[tid];
    sw2[tid] = g_w2c[tid];

    float acc[2][8][4];
    #pragma unroll
    for (int i = 0; i < 2; i++)
        #pragma unroll
        for (int j = 0; j < 8; j++)
            #pragma unroll
            for (int e = 0; e < 4; e++) acc[i][j][e] = 0.f;

    const char* gB = (const char*)g_B;
    const bool heavy = (ct == 0) && (wn == 0);

    auto stage_B = [&](int c, int buf) {
        uint32_t dbase = sb + buf * B_BUF_B;
        #pragma unroll
        for (int i = 0; i < 2; i++) {
            int flat = tid + i * 256;
            int u = flat & 3;
            int n = flat >> 2;
            uint32_t dst = dbase + n * 80 + u * 16;
            const char* src = gB + (size_t)((c * 320 + ct * 128 + n) * 64 + u * 16);
            CP16(dst, src);
        }
        if (ct == 0) {
            int u = tid & 3;
            int n = tid >> 2;
            uint32_t dst = dbase + (128 + n) * 80 + u * 16;
            const char* src = gB + (size_t)((c * 320 + 256 + n) * 64 + u * 16);
            CP16(dst, src);
        }
    };

    float4 av[4];
    auto load_x = [&](int c) {
        #pragma unroll
        for (int q = 0; q < 4; q++) {
            int row = q * 32 + (tid >> 3);
            int col = (tid & 7) * 4 + c * 32;
            av[q] = *(const float4*)(X + (size_t)(m0g + row) * 256 + col);
        }
    };
    auto convert_a = [&]() {
        #pragma unroll
        for (int q = 0; q < 4; q++) {
            int row = q * 32 + (tid >> 3);
            uint32_t off = row * 80 + (tid & 7) * 8;
            float v[4] = {av[q].x, av[q].y, av[q].z, av[q].w};
            unsigned short s1[4], s2[4];
            #pragma unroll
            for (int e = 0; e < 4; e++) {
                __nv_bfloat16 h1 = __float2bfloat16(v[e]);
                __nv_bfloat16 h2 = __float2bfloat16(v[e] - __bfloat162float(h1));
                s1[e] = __bfloat16_as_ushort(h1);
                s2[e] = __bfloat16_as_ushort(h2);
            }
            *(uint2*)(sm + SB_A + off) =
                make_uint2((unsigned)s1[0] | ((unsigned)s1[1] << 16),
                           (unsigned)s1[2] | ((unsigned)s1[3] << 16));
            if (ct == 0)
                *(uint2*)(sm + SB_A + A_LIMB_B + off) =
                    make_uint2((unsigned)s2[0] | ((unsigned)s2[1] << 16),
                               (unsigned)s2[2] | ((unsigned)s2[3] << 16));
        }
    };

    stage_B(0, 0); CP_COMMIT();
    load_x(0);

    for (int c = 0; c < 8; c++) {
        if (c < 7) { stage_B(c + 1, (c + 1) & 1); CP_COMMIT(); }
        convert_a();
        if (c < 7) load_x(c + 1);
        if (c < 7) { CP_WAIT(1); } else { CP_WAIT(0); }
        __syncthreads();

        uint32_t bbuf = sb + (c & 1) * B_BUF_B;
        #pragma unroll
        for (int ks = 0; ks < 2; ks++) {
            uint32_t acol = ks * 32 + ((lane >> 4) & 1) * 16;
            uint32_t arow = (wm * 32 + (lane & 15)) * 80;
            uint32_t arow2 = (wm * 32 + 16 + (lane & 15)) * 80;
            uint32_t a1r0[4], a1r1[4], a2r0[4], a2r1[4];
            ldsm_x4(a1r0, sb + SB_A + arow + acol);
            ldsm_x4(a1r1, sb + SB_A + arow2 + acol);
            if (heavy) {
                ldsm_x4(a2r0, sb + SB_A + A_LIMB_B + arow + acol);
                ldsm_x4(a2r1, sb + SB_A + A_LIMB_B + arow2 + acol);
            }
            const uint32_t koff = ks * 32 + ((lane >> 3) & 1) * 16;
            #pragma unroll
            for (int jj = 0; jj < 4; jj++) {
                uint32_t bfr[4];
                int rowb = wn * 64 + jj * 16 + ((lane >> 4) & 1) * 8 + (lane & 7);
                ldsm_x4(bfr, bbuf + rowb * 80 + koff);
                mma16816(acc[0][jj * 2],     a1r0, bfr);
                mma16816(acc[1][jj * 2],     a1r1, bfr);
                mma16816(acc[0][jj * 2 + 1], a1r0, bfr + 2);
                mma16816(acc[1][jj * 2 + 1], a1r1, bfr + 2);
                if (heavy) {
                    mma16816(acc[0][jj * 2],     a2r0, bfr);
                    mma16816(acc[1][jj * 2],     a2r1, bfr);
                    mma16816(acc[0][jj * 2 + 1], a2r0, bfr + 2);
                    mma16816(acc[1][jj * 2 + 1], a2r1, bfr + 2);
                    uint32_t bfr2[4];
                    int rowb2 = 128 + jj * 16 + ((lane >> 4) & 1) * 8 + (lane & 7);
                    ldsm_x4(bfr2, bbuf + rowb2 * 80 + koff);
                    mma16816(acc[0][jj * 2],     a1r0, bfr2);
                    mma16816(acc[1][jj * 2],     a1r1, bfr2);
                    mma16816(acc[0][jj * 2 + 1], a1r0, bfr2 + 2);
                    mma16816(acc[1][jj * 2 + 1], a1r1, bfr2 + 2);
                }
            }
        }
        __syncthreads();
    }

    const int g = ct * 2 + wn;
    const bool is_relu = (g == 0);
    const int cbase = ct * 128 + wn * 64;
    const float b2 = g_b2c[g];

    #pragma unroll
    for (int mf = 0; mf < 2; mf++) {
        float p0 = 0.f, p1 = 0.f;
        #pragma unroll
        for (int j = 0; j < 8; j++) {
            int c0 = cbase + j * 8 + (lane & 3) * 2;
            float v0 = acc[mf][j][0] + sb1[c0];
            float v1 = acc[mf][j][1] + sb1[c0 + 1];
            float v2 = acc[mf][j][2] + sb1[c0];
            float v3 = acc[mf][j][3] + sb1[c0 + 1];
            float f0 = is_relu ? fmaxf(v0, 0.f) : tanh_fast(v0);
            float f1 = is_relu ? fmaxf(v1, 0.f) : tanh_fast(v1);
            float f2 = is_relu ? fmaxf(v2, 0.f) : tanh_fast(v2);
            float f3 = is_relu ? fmaxf(v3, 0.f) : tanh_fast(v3);
            p0 = fmaf(f0, sw2[c0], p0);
            p0 = fmaf(f1, sw2[c0 + 1], p0);
            p1 = fmaf(f2, sw2[c0], p1);
            p1 = fmaf(f3, sw2[c0 + 1], p1);
        }
        p0 += __shfl_xor_sync(0xffffffff, p0, 1);
        p0 += __shfl_xor_sync(0xffffffff, p0, 2);
        p1 += __shfl_xor_sync(0xffffffff, p1, 1);
        p1 += __shfl_xor_sync(0xffffffff, p1, 2);
        if ((lane & 3) == 0) {
            int m = m0g + wm * 32 + mf * 16 + (lane >> 2);
            g_scores[(size_t)g * Mc + m]     = p0 + b2;
            g_scores[(size_t)g * Mc + m + 8] = p1 + b2;
        }
    }
}

// ---------------- K2: per-batch top-k, softmax, diagnostics (1024 thr) ----------------
__global__ void __launch_bounds__(1024) k_perbatch(const float* __restrict__ mask,
                                                   float* __restrict__ out) {
    const int b = blockIdx.x;
    const int t = threadIdx.x;
    const int n0 = t * 2;

    __shared__ unsigned s_key[2048];
    __shared__ unsigned s_hist[256];
    __shared__ float    s_wf[3 * 33];
    __shared__ int      s_wi[33];
    __shared__ unsigned s_bc[2];

    float mk[2];
    mk[0] = mask[b * Nc + n0];
    mk[1] = mask[b * Nc + n0 + 1];

    float cnt = bsum1024(mk[0] + mk[1], s_wf);
    float inv_mean = 1.f / fmaxf(cnt, 1.f);

    #pragma unroll
    for (int q = 0; q < 2; q++) {
        float sc = g_scores[(size_t)b * Nc + n0 + q];
        if (mk[q] == 0.f) sc = NEG_INF_F;
        s_key[n0 + q] = f2key(sc);
    }
    __syncthreads();

    unsigned T = radix1024(s_key, KTOP, s_hist, s_bc);

    int lg = 0, le = 0;
    unsigned uk[2];
    #pragma unroll
    for (int q = 0; q < 2; q++) {
        uk[q] = s_key[n0 + q];
        lg += (uk[q] > T);
        le += (uk[q] == T);
    }
    int cg = bisum1024(lg, s_wi);
    int need = KTOP - cg;
    int excl = bexscan1024(le, s_wi);

    float tmv[2];
    float lc = 0.f;
    int rank = excl;
    #pragma unroll
    for (int q = 0; q < 2; q++) {
        float tmq = 0.f;
        if (uk[q] > T) tmq = 1.f;
        else if (uk[q] == T) { if (rank < need) tmq = 1.f; rank++; }
        tmv[q] = tmq;
        out[OUT_TOPK + b * Nc + n0 + q] = tmq;
        lc += tmq * mk[q];
    }
    float csum = bsum1024(lc, s_wf);
    float invden = 1.f / fmaxf(csum, 1.f);
    #pragma unroll
    for (int q = 0; q < 2; q++) {
        g_poolw[((size_t)b * 5 + 0) * Nc + n0 + q] = mk[q] * inv_mean;
        g_poolw[((size_t)b * 5 + 1) * Nc + n0 + q] = tmv[q] * mk[q] * invden;
    }

    float sc3[3][2];
    float lm[3] = {-3e38f, -3e38f, -3e38f};
    #pragma unroll
    for (int k = 0; k < 3; k++)
        #pragma unroll
        for (int q = 0; q < 2; q++) {
            float s = g_scores[(size_t)(1 + k) * Mc + b * Nc + n0 + q];
            if (mk[q] == 0.f) s = NEG_INF_F;
            sc3[k][q] = s;
            lm[k] = fmaxf(lm[k], s);
        }
    bmaxv<3>(lm, s_wf);
    float ls[3] = {0.f, 0.f, 0.f};
    #pragma unroll
    for (int k = 0; k < 3; k++)
        #pragma unroll
        for (int q = 0; q < 2; q++) {
            sc3[k][q] = expf(sc3[k][q] - lm[k]);
            ls[k] += sc3[k][q];
        }
    bsumv<3>(ls, s_wf);

    float avq[2] = {0.f, 0.f};
    #pragma unroll
    for (int k = 0; k < 3; k++) {
        float inv = 1.f / ls[k];
        #pragma unroll
        for (int q = 0; q < 2; q++) {
            float a = (mk[q] == 0.f) ? 0.f : sc3[k][q] * inv;
            out[OUT_ALLA + ((size_t)b * NBc + k) * Nc + n0 + q] = a;
            g_poolw[((size_t)b * 5 + 2 + k) * Nc + n0 + q] = a;
            avq[q] += a;
        }
    }
    #pragma unroll
    for (int q = 0; q < 2; q++) avq[q] *= (1.f / 3.f);

    float es[2] = {0.f, 0.f};
    #pragma unroll
    for (int q = 0; q < 2; q++) {
        out[OUT_AVG + b * Nc + n0 + q] = avq[q];
        es[0] += avq[q] * logf(avq[q] + 1e-8f);
        es[1] += avq[q] * avq[q];
        s_key[n0 + q] = f2key(avq[q]);
    }
    bsumv<2>(es, s_wf);   // also fences s_key writes
    if (t == 0) {
        out[OUT_ENT + b] = -es[0];
        out[OUT_EFF + b] = 1.f / es[1];
    }
    __syncthreads();

    unsigned T5 = radix1024(s_key, K5, s_hist, s_bc);
    int lg5 = 0;
    float lsum5 = 0.f;
    #pragma unroll
    for (int q = 0; q < 2; q++) {
        unsigned u = s_key[n0 + q];
        if (u > T5) { lg5++; lsum5 += avq[q]; }
    }
    int cg5 = bisum1024(lg5, s_wi);
    float sgt = bsum1024(lsum5, s_wf);
    if (t == 0)
        out[OUT_T5 + b] = sgt + (float)(K5 - cg5) * key2f(T5);
}

// ---------------- K3: pooling (exact R8/R11 version) ----------------
__global__ void __launch_bounds__(256) k_pool2(const float* __restrict__ X) {
    const int b = blockIdx.x >> 3;
    const int seg = blockIdx.x & 7;
    const int tid = threadIdx.x;
    const int tx = tid & 63;
    const int rg = tid >> 6;
    __shared__ float sw[5][256];
    __shared__ float part[4][5][256];

    #pragma unroll
    for (int p = 0; p < 5; p++)
        sw[p][tid] = g_poolw[((size_t)b * 5 + p) * Nc + seg * 256 + tid];
    __syncthreads();

    const float* xb = X + ((size_t)(b * Nc + seg * 256 + rg * 64)) * Dc + tx * 4;
    float4 a0 = {0,0,0,0}, a1 = {0,0,0,0}, a2 = {0,0,0,0}, a3 = {0,0,0,0}, a4 = {0,0,0,0};
    #pragma unroll 4
    for (int n = 0; n < 64; n++) {
        float4 xv = *(const float4*)(xb + (size_t)n * Dc);
        float w0 = sw[0][rg * 64 + n], w1 = sw[1][rg * 64 + n], w2 = sw[2][rg * 64 + n];
        float w3 = sw[3][rg * 64 + n], w4 = sw[4][rg * 64 + n];
        a0.x = fmaf(xv.x, w0, a0.x); a0.y = fmaf(xv.y, w0, a0.y);
        a0.z = fmaf(xv.z, w0, a0.z); a0.w = fmaf(xv.w, w0, a0.w);
        a1.x = fmaf(xv.x, w1, a1.x); a1.y = fmaf(xv.y, w1, a1.y);
        a1.z = fmaf(xv.z, w1, a1.z); a1.w = fmaf(xv.w, w1, a1.w);
        a2.x = fmaf(xv.x, w2, a2.x); a2.y = fmaf(xv.y, w2, a2.y);
        a2.z = fmaf(xv.z, w2, a2.z); a2.w = fmaf(xv.w, w2, a2.w);
        a3.x = fmaf(xv.x, w3, a3.x); a3.y = fmaf(xv.y, w3, a3.y);
        a3.z = fmaf(xv.z, w3, a3.z); a3.w = fmaf(xv.w, w3, a3.w);
        a4.x = fmaf(xv.x, w4, a4.x); a4.y = fmaf(xv.y, w4, a4.y);
        a4.z = fmaf(xv.z, w4, a4.z); a4.w = fmaf(xv.w, w4, a4.w);
    }
    *(float4*)&part[rg][0][tx * 4] = a0;
    *(float4*)&part[rg][1][tx * 4] = a1;
    *(float4*)&part[rg][2][tx * 4] = a2;
    *(float4*)&part[rg][3][tx * 4] = a3;
    *(float4*)&part[rg][4][tx * 4] = a4;
    __syncthreads();

    float* dst = g_poolpart + ((size_t)(b * NSEG + seg)) * 1280;
    #pragma unroll
    for (int p = 0; p < 5; p++) {
        float s = part[0][p][tid] + part[1][p][tid] + part[2][p][tid] + part[3][p][tid];
        dst[p * 256 + tid] = s;
    }
}

// ---------------- K4a: fusion GEMV1 partials (2 batch rows per block) ----------------
__global__ void __launch_bounds__(512) k_fuse1(const float* __restrict__ Wf1) {
    const int bp = blockIdx.x >> 2;
    const int seg = blockIdx.x & 3;
    const int c = threadIdx.x;
    const int b0 = bp * 2, b1 = b0 + 1;
    __shared__ float sc0[320];
    __shared__ float sc1[320];

    for (int i = c; i < 320; i += 512) {
        int gi = seg * 320 + i;
        float s0 = 0.f, s1 = 0.f;
        #pragma unroll
        for (int se = 0; se < NSEG; se++) {
            s0 += g_poolpart[((size_t)(b0 * NSEG + se)) * 1280 + gi];
            s1 += g_poolpart[((size_t)(b1 * NSEG + se)) * 1280 + gi];
        }
        sc0[i] = s0;
        sc1[i] = s1;
    }
    __syncthreads();

    float acc0 = 0.f, acc1 = 0.f;
    const float* W = Wf1 + (size_t)(seg * 320) * TWOD + c;
    #pragma unroll 8
    for (int j = 0; j < 320; j++) {
        float w = W[(size_t)j * TWOD];
        acc0 = fmaf(sc0[j], w, acc0);
        acc1 = fmaf(sc1[j], w, acc1);
    }
    g_fpart[(b0 * 4 + seg) * TWOD + c] = acc0;
    g_fpart[(b1 * 4 + seg) * TWOD + c] = acc1;
}

// ---------------- K4b: reduce + LN + GELU + GEMV2 (2 batch rows per block) ----------------
__global__ void __launch_bounds__(512) k_fuse2(const float* __restrict__ bf1,
                                               const float* __restrict__ lng,
                                               const float* __restrict__ lnb,
                                               const float* __restrict__ Wf2,
                                               const float* __restrict__ bf2,
                                               float* __restrict__ out) {
    const int bp = blockIdx.x;
    const int c = threadIdx.x;
    const int b0 = bp * 2, b1 = b0 + 1;
    __shared__ float sx0[TWOD];
    __shared__ float sx1[TWOD];
    __shared__ float red[TWOD];

    float bb = bf1[c];
    float acc0 = bb, acc1 = bb;
    #pragma unroll
    for (int seg = 0; seg < 4; seg++) {
        acc0 += g_fpart[(b0 * 4 + seg) * TWOD + c];
        acc1 += g_fpart[(b1 * 4 + seg) * TWOD + c];
    }

    float gln = lng[c], bln = lnb[c];

    red[c] = acc0; __syncthreads();
    #pragma unroll
    for (int s = 256; s > 0; s >>= 1) { if (c < s) red[c] += red[c + s]; __syncthreads(); }
    float mu0 = red[0] / (float)TWOD;
    __syncthreads();
    float dv0 = acc0 - mu0;
    red[c] = dv0 * dv0; __syncthreads();
    #pragma unroll
    for (int s = 256; s > 0; s >>= 1) { if (c < s) red[c] += red[c + s]; __syncthreads(); }
    float var0 = red[0] / (float)TWOD;
    __syncthreads();
    float x0 = dv0 * rsqrtf(var0 + 1e-5f) * gln + bln;
    sx0[c] = 0.5f * x0 * (1.f + erff(x0 * 0.70710678118654752f));

    red[c] = acc1; __syncthreads();
    #pragma unroll
    for (int s = 256; s > 0; s >>= 1) { if (c < s) red[c] += red[c + s]; __syncthreads(); }
    float mu1 = red[0] / (float)TWOD;
    __syncthreads();
    float dv1 = acc1 - mu1;
    red[c] = dv1 * dv1; __syncthreads();
    #pragma unroll
    for (int s = 256; s > 0; s >>= 1) { if (c < s) red[c] += red[c + s]; __syncthreads(); }
    float var1 = red[0] / (float)TWOD;
    __syncthreads();
    float x1 = dv1 * rsqrtf(var1 + 1e-5f) * gln + bln;
    sx1[c] = 0.5f * x1 * (1.f + erff(x1 * 0.70710678118654752f));
    __syncthreads();

    float o0 = bf2[c], o1 = o0;
    #pragma unroll 8
    for (int j = 0; j < TWOD; j++) {
        float w = Wf2[(size_t)j * TWOD + c];
        o0 = fmaf(sx0[j], w, o0);
        o1 = fmaf(sx1[j], w, o1);
    }
    out[OUT_BAG + b0 * TWOD + c] = o0;
    out[OUT_BAG + b1 * TWOD + c] = o1;
}

// ---------------- launch ----------------
extern "C" void kernel_launch(void* const* d_in, const int* in_sizes, int n_in,
                              void* d_out, int out_size) {
    const float* inst = (const float*)d_in[0];
    const float* mask = (const float*)d_in[1];
    const float* Ws1 = (const float*)d_in[2];
    const float* bs1 = (const float*)d_in[3];
    const float* Ws2 = (const float*)d_in[4];
    const float* bs2 = (const float*)d_in[5];
    const float* Wa1 = (const float*)d_in[6];
    const float* ba1 = (const float*)d_in[7];
    const float* Wa2 = (const float*)d_in[8];
    const float* ba2 = (const float*)d_in[9];
    const float* Wf1 = (const float*)d_in[10];
    const float* bf1 = (const float*)d_in[11];
    const float* lng = (const float*)d_in[12];
    const float* lnb = (const float*)d_in[13];
    const float* Wf2 = (const float*)d_in[14];
    const float* bf2 = (const float*)d_in[15];
    float* out = (float*)d_out;

    static bool attr_done = false;
    if (!attr_done) {
        cudaFuncSetAttribute(k_gemm_mma, cudaFuncAttributeMaxDynamicSharedMemorySize, SMEM_DYN);
        attr_done = true;
    }

    k_prep<<<321, 256>>>(Ws1, Wa1, bs1, Ws2, bs2, ba1, Wa2, ba2);
    k_gemm_mma<<<dim3(2, Mc / 128), 256, SMEM_DYN>>>(inst);
    k_perbatch<<<Bc, 1024>>>(mask, out);
    k_pool2<<<Bc * NSEG, 256>>>(inst);
    k_fuse1<<<(Bc / 2) * 4, 512>>>(Wf1);
    k_fuse2<<<Bc / 2, 512>>>(bf1, lng, lnb, Wf2, bf2, out);
}

// round 17
// speedup vs baseline: 1.0833x; 1.0050x over previous
#include <cuda_runtime.h>
#include <cuda_bf16.h>
#include <math.h>
#include <stdint.h>

#define Bc   64
#define Nc   2048
#define Dc   256
#define Hc   64
#define NBc  3
#define Mc   (Bc * Nc)
#define KTOP 204
#define K5   102
#define TWOD 512
#define CATD 1280
#define NEG_INF_F (-1e30f)

#define OUT_BAG   0
#define OUT_ALLA  (OUT_BAG  + Bc * TWOD)
#define OUT_AVG   (OUT_ALLA + Bc * NBc * Nc)
#define OUT_TOPK  (OUT_AVG  + Bc * Nc)
#define OUT_ENT   (OUT_TOPK + Bc * Nc)
#define OUT_EFF   (OUT_ENT  + Bc)
#define OUT_T5    (OUT_EFF  + Bc)

// ---- GEMM smem layout (R11 2-CTA form) ----
#define B_BUF_B    15360
#define A_LIMB_B   10240
#define SB_A       30720
#define SB_SCAL    51200
#define SMEM_DYN   (51200 + 2048)
#define NSEG       8

// ---------------- device scratch ----------------
__device__ __nv_bfloat16 g_B[8 * 320 * 32];   // [chunk][row: 256 b1 + 64 b2scorer][k]
__device__ float g_b1c[256];
__device__ float g_w2c[256];
__device__ float g_b2c[4];
__device__ float g_scores[4L * Mc];           // [group][m]
__device__ float g_poolw[(long)Bc * 5 * Nc];
__device__ float g_poolpart[Bc * NSEG * 5 * 256];
__device__ float g_fpart[Bc * 4 * TWOD];

// ---------------- helpers ----------------
__device__ __forceinline__ uint32_t smem_u32(const void* p) {
    uint32_t a;
    asm("{ .reg .u64 t; cvta.to.shared.u64 t, %1; cvt.u32.u64 %0, t; }" : "=r"(a) : "l"(p));
    return a;
}
__device__ __forceinline__ void ldsm_x4(uint32_t* r, uint32_t addr) {
    asm volatile("ldmatrix.sync.aligned.m8n8.x4.shared.b16 {%0,%1,%2,%3}, [%4];"
        : "=r"(r[0]), "=r"(r[1]), "=r"(r[2]), "=r"(r[3]) : "r"(addr));
}
__device__ __forceinline__ void mma16816(float* d, const uint32_t* a, const uint32_t* b) {
    asm volatile(
        "mma.sync.aligned.m16n8k16.row.col.f32.bf16.bf16.f32 "
        "{%0,%1,%2,%3}, {%4,%5,%6,%7}, {%8,%9}, {%0,%1,%2,%3};"
        : "+f"(d[0]), "+f"(d[1]), "+f"(d[2]), "+f"(d[3])
        : "r"(a[0]), "r"(a[1]), "r"(a[2]), "r"(a[3]), "r"(b[0]), "r"(b[1]));
}
#define CP16(dst, src) asm volatile("cp.async.cg.shared.global [%0], [%1], 16;" :: "r"(dst), "l"(src))
#define CP_COMMIT()    asm volatile("cp.async.commit_group;" ::: "memory")
#define CP_WAIT(n)     asm volatile("cp.async.wait_group %0;" :: "n"(n) : "memory")

__device__ __forceinline__ float tanh_fast(float x) {
    float y;
    asm("tanh.approx.f32 %0, %1;" : "=f"(y) : "f"(x));
    return y;
}
__device__ __forceinline__ unsigned f2key(float f) {
    unsigned u = __float_as_uint(f);
    return (u & 0x80000000u) ? ~u : (u | 0x80000000u);
}
__device__ __forceinline__ float key2f(unsigned k) {
    unsigned u = (k & 0x80000000u) ? (k & 0x7FFFFFFFu) : ~k;
    return __uint_as_float(u);
}

// ---- 1024-thread block reductions (warp shuffle, two-level) ----
__device__ __forceinline__ float bsum1024(float v, float* sw) {
    int lane = threadIdx.x & 31, wid = threadIdx.x >> 5;
    #pragma unroll
    for (int o = 16; o; o >>= 1) v += __shfl_xor_sync(0xffffffffu, v, o);
    if (!lane) sw[wid] = v;
    __syncthreads();
    if (wid == 0) {
        float x = sw[lane];
        #pragma unroll
        for (int o = 16; o; o >>= 1) x += __shfl_xor_sync(0xffffffffu, x, o);
        if (!lane) sw[32] = x;
    }
    __syncthreads();
    float r = sw[32];
    __syncthreads();
    return r;
}
template<int NV>
__device__ __forceinline__ void bsumv(float* v, float* sw) {
    int lane = threadIdx.x & 31, wid = threadIdx.x >> 5;
    #pragma unroll
    for (int o = 16; o; o >>= 1)
        #pragma unroll
        for (int i = 0; i < NV; i++) v[i] += __shfl_xor_sync(0xffffffffu, v[i], o);
    if (!lane)
        #pragma unroll
        for (int i = 0; i < NV; i++) sw[i * 33 + wid] = v[i];
    __syncthreads();
    if (wid == 0) {
        float x[NV];
        #pragma unroll
        for (int i = 0; i < NV; i++) x[i] = sw[i * 33 + lane];
        #pragma unroll
        for (int o = 16; o; o >>= 1)
            #pragma unroll
            for (int i = 0; i < NV; i++) x[i] += __shfl_xor_sync(0xffffffffu, x[i], o);
        if (!lane)
            #pragma unroll
            for (int i = 0; i < NV; i++) sw[i * 33 + 32] = x[i];
    }
    __syncthreads();
    #pragma unroll
    for (int i = 0; i < NV; i++) v[i] = sw[i * 33 + 32];
    __syncthreads();
}
template<int NV>
__device__ __forceinline__ void bmaxv(float* v, float* sw) {
    int lane = threadIdx.x & 31, wid = threadIdx.x >> 5;
    #pragma unroll
    for (int o = 16; o; o >>= 1)
        #pragma unroll
        for (int i = 0; i < NV; i++) v[i] = fmaxf(v[i], __shfl_xor_sync(0xffffffffu, v[i], o));
    if (!lane)
        #pragma unroll
        for (int i = 0; i < NV; i++) sw[i * 33 + wid] = v[i];
    __syncthreads();
    if (wid == 0) {
        float x[NV];
        #pragma unroll
        for (int i = 0; i < NV; i++) x[i] = sw[i * 33 + lane];
        #pragma unroll
        for (int o = 16; o; o >>= 1)
            #pragma unroll
            for (int i = 0; i < NV; i++) x[i] = fmaxf(x[i], __shfl_xor_sync(0xffffffffu, x[i], o));
        if (!lane)
            #pragma unroll
            for (int i = 0; i < NV; i++) sw[i * 33 + 32] = x[i];
    }
    __syncthreads();
    #pragma unroll
    for (int i = 0; i < NV; i++) v[i] = sw[i * 33 + 32];
    __syncthreads();
}
__device__ __forceinline__ int bisum1024(int v, int* sw) {
    int lane = threadIdx.x & 31, wid = threadIdx.x >> 5;
    #pragma unroll
    for (int o = 16; o; o >>= 1) v += __shfl_xor_sync(0xffffffffu, v, o);
    if (!lane) sw[wid] = v;
    __syncthreads();
    if (wid == 0) {
        int x = sw[lane];
        #pragma unroll
        for (int o = 16; o; o >>= 1) x += __shfl_xor_sync(0xffffffffu, x, o);
        if (!lane) sw[32] = x;
    }
    __syncthreads();
    int r = sw[32];
    __syncthreads();
    return r;
}
__device__ __forceinline__ int bexscan1024(int v, int* sw) {
    int lane = threadIdx.x & 31, wid = threadIdx.x >> 5;
    int x = v;
    #pragma unroll
    for (int o = 1; o < 32; o <<= 1) {
        int y = __shfl_up_sync(0xffffffffu, x, o);
        if (lane >= o) x += y;
    }
    if (lane == 31) sw[wid] = x;
    __syncthreads();
    if (wid == 0) {
        int w = sw[lane], inc = w;
        #pragma unroll
        for (int o = 1; o < 32; o <<= 1) {
            int y = __shfl_up_sync(0xffffffffu, inc, o);
            if (lane >= o) inc += y;
        }
        sw[lane] = inc - w;
    }
    __syncthreads();
    int r = sw[wid] + x - v;
    __syncthreads();
    return r;
}

// exact K-th largest among 2048 keys; 1024 threads, 2 keys each.
__device__ unsigned radix1024(const unsigned* keys, int K,
                              unsigned* hist, volatile unsigned* bc) {
    const int t = threadIdx.x;
    const int n0 = t * 2;
    unsigned prefix = 0;
    int rem = K;
    for (int pass = 0; pass < 4; pass++) {
        const int shift = 24 - 8 * pass;
        const unsigned hm = pass ? (0xFFFFFFFFu << (shift + 8)) : 0u;
        if (t < 256) hist[t] = 0;
        __syncthreads();
        #pragma unroll
        for (int q = 0; q < 2; q++) {
            unsigned u = keys[n0 + q];
            if ((u & hm) == prefix) atomicAdd(&hist[(u >> shift) & 255u], 1u);
        }
        __syncthreads();
        if (t < 32) {
            int base = t * 8;
            int v[8], s = 0;
            #pragma unroll
            for (int i = 0; i < 8; i++) { v[i] = (int)hist[255 - (base + i)]; s += v[i]; }
            int inc = s;
            #pragma unroll
            for (int o = 1; o < 32; o <<= 1) {
                int y = __shfl_up_sync(0xffffffffu, inc, o);
                if (t >= o) inc += y;
            }
            int run = inc - s;
            #pragma unroll
            for (int i = 0; i < 8; i++) {
                int prev = run;
                run += v[i];
                if (run >= rem && prev < rem) {
                    bc[0] = prefix | ((unsigned)(255 - (base + i)) << shift);
                    bc[1] = (unsigned)(rem - prev);
                }
            }
        }
        __syncthreads();
        prefix = bc[0];
        rem = (int)bc[1];
        __syncthreads();
    }
    return prefix;
}

// ---------------- K0: weight image + scalars ----------------
__global__ void k_prep(const float* __restrict__ Ws1, const float* __restrict__ Wa1,
                       const float* __restrict__ bs1, const float* __restrict__ Ws2,
                       const float* __restrict__ bs2, const float* __restrict__ ba1,
                       const float* __restrict__ Wa2, const float* __restrict__ ba2) {
    if (blockIdx.x == 320) {
        int t = threadIdx.x;
        int g = t >> 6, ch = t & 63;
        g_b1c[t] = (g == 0) ? bs1[ch] : ba1[(g - 1) * Hc + ch];
        g_w2c[t] = (g == 0) ? Ws2[ch] : Wa2[(g - 1) * Hc + ch];
        if (t < 4) g_b2c[t] = (t == 0) ? bs2[0] : ba2[t - 1];
        return;
    }
    int gid = blockIdx.x * 256 + threadIdx.x;   // < 81920
    int k = gid & 31;
    int row = (gid >> 5) % 320;
    int c = gid / 10240;                        // chunk
    int kg = c * 32 + k;
    float w;
    bool resid = (row >= 256);
    int n = resid ? (row - 256) : row;
    if (n < 64) w = Ws1[kg * 64 + n];
    else {
        int br = (n - 64) >> 6, h = (n - 64) & 63;
        w = Wa1[(br * 256 + kg) * 64 + h];
    }
    __nv_bfloat16 h1 = __float2bfloat16(w);
    __nv_bfloat16 v = resid ? __float2bfloat16(w - __bfloat162float(h1)) : h1;
    g_B[gid] = v;
}

// ---------------- K1: split-bf16 HMMA scorer GEMM (exact R11 2-CTA form) ----------------
__global__ void __launch_bounds__(256, 2) k_gemm_mma(const float* __restrict__ X) {
    extern __shared__ char sm[];
    const int tid = threadIdx.x;
    const int lane = tid & 31;
    const int wid = tid >> 5;
    const int wm = wid & 3;
    const int wn = wid >> 2;
    const int m0g = blockIdx.y * 128;
    const int ct = blockIdx.x;
    const uint32_t sb = smem_u32(sm);
    float* sb1 = (float*)(sm + SB_SCAL);
    float* sw2 = sb1 + 256;

    sb1[tid] = g_b1c[tid];
    sw2[tid] = g_w2c[tid];

    float acc[2][8][4];
    #pragma unroll
    for (int i = 0; i < 2; i++)
        #pragma unroll
        for (int j = 0; j < 8; j++)
            #pragma unroll
            for (int e = 0; e < 4; e++) acc[i][j][e] = 0.f;

    const char* gB = (const char*)g_B;
    const bool heavy = (ct == 0) && (wn == 0);

    auto stage_B = [&](int c, int buf) {
        uint32_t dbase = sb + buf * B_BUF_B;
        #pragma unroll
        for (int i = 0; i < 2; i++) {
            int flat = tid + i * 256;
            int u = flat & 3;
            int n = flat >> 2;
            uint32_t dst = dbase + n * 80 + u * 16;
            const char* src = gB + (size_t)((c * 320 + ct * 128 + n) * 64 + u * 16);
            CP16(dst, src);
        }
        if (ct == 0) {
            int u = tid & 3;
            int n = tid >> 2;
            uint32_t dst = dbase + (128 + n) * 80 + u * 16;
            const char* src = gB + (size_t)((c * 320 + 256 + n) * 64 + u * 16);
            CP16(dst, src);
        }
    };

    float4 av[4];
    auto load_x = [&](int c) {
        #pragma unroll
        for (int q = 0; q < 4; q++) {
            int row = q * 32 + (tid >> 3);
            int col = (tid & 7) * 4 + c * 32;
            av[q] = *(const float4*)(X + (size_t)(m0g + row) * 256 + col);
        }
    };
    auto convert_a = [&]() {
        #pragma unroll
        for (int q = 0; q < 4; q++) {
            int row = q * 32 + (tid >> 3);
            uint32_t off = row * 80 + (tid & 7) * 8;
            float v[4] = {av[q].x, av[q].y, av[q].z, av[q].w};
            unsigned short s1[4], s2[4];
            #pragma unroll
            for (int e = 0; e < 4; e++) {
                __nv_bfloat16 h1 = __float2bfloat16(v[e]);
                __nv_bfloat16 h2 = __float2bfloat16(v[e] - __bfloat162float(h1));
                s1[e] = __bfloat16_as_ushort(h1);
                s2[e] = __bfloat16_as_ushort(h2);
            }
            *(uint2*)(sm + SB_A + off) =
                make_uint2((unsigned)s1[0] | ((unsigned)s1[1] << 16),
                           (unsigned)s1[2] | ((unsigned)s1[3] << 16));
            if (ct == 0)
                *(uint2*)(sm + SB_A + A_LIMB_B + off) =
                    make_uint2((unsigned)s2[0] | ((unsigned)s2[1] << 16),
                               (unsigned)s2[2] | ((unsigned)s2[3] << 16));
        }
    };

    stage_B(0, 0); CP_COMMIT();
    load_x(0);

    for (int c = 0; c < 8; c++) {
        if (c < 7) { stage_B(c + 1, (c + 1) & 1); CP_COMMIT(); }
        convert_a();
        if (c < 7) load_x(c + 1);
        if (c < 7) { CP_WAIT(1); } else { CP_WAIT(0); }
        __syncthreads();

        uint32_t bbuf = sb + (c & 1) * B_BUF_B;
        #pragma unroll
        for (int ks = 0; ks < 2; ks++) {
            uint32_t acol = ks * 32 + ((lane >> 4) & 1) * 16;
            uint32_t arow = (wm * 32 + (lane & 15)) * 80;
            uint32_t arow2 = (wm * 32 + 16 + (lane & 15)) * 80;
            uint32_t a1r0[4], a1r1[4], a2r0[4], a2r1[4];
            ldsm_x4(a1r0, sb + SB_A + arow + acol);
            ldsm_x4(a1r1, sb + SB_A + arow2 + acol);
            if (heavy) {
                ldsm_x4(a2r0, sb + SB_A + A_LIMB_B + arow + acol);
                ldsm_x4(a2r1, sb + SB_A + A_LIMB_B + arow2 + acol);
            }
            const uint32_t koff = ks * 32 + ((lane >> 3) & 1) * 16;
            #pragma unroll
            for (int jj = 0; jj < 4; jj++) {
                uint32_t bfr[4];
                int rowb = wn * 64 + jj * 16 + ((lane >> 4) & 1) * 8 + (lane & 7);
                ldsm_x4(bfr, bbuf + rowb * 80 + koff);
                mma16816(acc[0][jj * 2],     a1r0, bfr);
                mma16816(acc[1][jj * 2],     a1r1, bfr);
                mma16816(acc[0][jj * 2 + 1], a1r0, bfr + 2);
                mma16816(acc[1][jj * 2 + 1], a1r1, bfr + 2);
                if (heavy) {
                    mma16816(acc[0][jj * 2],     a2r0, bfr);
                    mma16816(acc[1][jj * 2],     a2r1, bfr);
                    mma16816(acc[0][jj * 2 + 1], a2r0, bfr + 2);
                    mma16816(acc[1][jj * 2 + 1], a2r1, bfr + 2);
                    uint32_t bfr2[4];
                    int rowb2 = 128 + jj * 16 + ((lane >> 4) & 1) * 8 + (lane & 7);
                    ldsm_x4(bfr2, bbuf + rowb2 * 80 + koff);
                    mma16816(acc[0][jj * 2],     a1r0, bfr2);
                    mma16816(acc[1][jj * 2],     a1r1, bfr2);
                    mma16816(acc[0][jj * 2 + 1], a1r0, bfr2 + 2);
                    mma16816(acc[1][jj * 2 + 1], a1r1, bfr2 + 2);
                }
            }
        }
        __syncthreads();
    }

    const int g = ct * 2 + wn;
    const bool is_relu = (g == 0);
    const int cbase = ct * 128 + wn * 64;
    const float b2 = g_b2c[g];

    #pragma unroll
    for (int mf = 0; mf < 2; mf++) {
        float p0 = 0.f, p1 = 0.f;
        #pragma unroll
        for (int j = 0; j < 8; j++) {
            int c0 = cbase + j * 8 + (lane & 3) * 2;
            float v0 = acc[mf][j][0] + sb1[c0];
            float v1 = acc[mf][j][1] + sb1[c0 + 1];
            float v2 = acc[mf][j][2] + sb1[c0];
            float v3 = acc[mf][j][3] + sb1[c0 + 1];
            float f0 = is_relu ? fmaxf(v0, 0.f) : tanh_fast(v0);
            float f1 = is_relu ? fmaxf(v1, 0.f) : tanh_fast(v1);
            float f2 = is_relu ? fmaxf(v2, 0.f) : tanh_fast(v2);
            float f3 = is_relu ? fmaxf(v3, 0.f) : tanh_fast(v3);
            p0 = fmaf(f0, sw2[c0], p0);
            p0 = fmaf(f1, sw2[c0 + 1], p0);
            p1 = fmaf(f2, sw2[c0], p1);
            p1 = fmaf(f3, sw2[c0 + 1], p1);
        }
        p0 += __shfl_xor_sync(0xffffffff, p0, 1);
        p0 += __shfl_xor_sync(0xffffffff, p0, 2);
        p1 += __shfl_xor_sync(0xffffffff, p1, 1);
        p1 += __shfl_xor_sync(0xffffffff, p1, 2);
        if ((lane & 3) == 0) {
            int m = m0g + wm * 32 + mf * 16 + (lane >> 2);
            g_scores[(size_t)g * Mc + m]     = p0 + b2;
            g_scores[(size_t)g * Mc + m + 8] = p1 + b2;
        }
    }
}

// ---------------- K2: per-batch top-k, softmax, diagnostics (1024 thr, float2 I/O) ----------------
__global__ void __launch_bounds__(1024) k_perbatch(const float* __restrict__ mask,
                                                   float* __restrict__ out) {
    const int b = blockIdx.x;
    const int t = threadIdx.x;
    const int n0 = t * 2;

    __shared__ unsigned s_key[2048];
    __shared__ unsigned s_hist[256];
    __shared__ float    s_wf[3 * 33];
    __shared__ int      s_wi[33];
    __shared__ unsigned s_bc[2];

    float2 mk2 = *(const float2*)(mask + b * Nc + n0);
    float mk[2] = {mk2.x, mk2.y};

    float cnt = bsum1024(mk[0] + mk[1], s_wf);
    float inv_mean = 1.f / fmaxf(cnt, 1.f);

    {
        float2 sc2 = *(const float2*)(g_scores + (size_t)b * Nc + n0);
        float scq[2] = {sc2.x, sc2.y};
        #pragma unroll
        for (int q = 0; q < 2; q++) {
            if (mk[q] == 0.f) scq[q] = NEG_INF_F;
            s_key[n0 + q] = f2key(scq[q]);
        }
    }
    __syncthreads();

    unsigned T = radix1024(s_key, KTOP, s_hist, s_bc);

    int lg = 0, le = 0;
    unsigned uk[2];
    #pragma unroll
    for (int q = 0; q < 2; q++) {
        uk[q] = s_key[n0 + q];
        lg += (uk[q] > T);
        le += (uk[q] == T);
    }
    int cg = bisum1024(lg, s_wi);
    int need = KTOP - cg;
    int excl = bexscan1024(le, s_wi);

    float tmv[2];
    float lc = 0.f;
    int rank = excl;
    #pragma unroll
    for (int q = 0; q < 2; q++) {
        float tmq = 0.f;
        if (uk[q] > T) tmq = 1.f;
        else if (uk[q] == T) { if (rank < need) tmq = 1.f; rank++; }
        tmv[q] = tmq;
        lc += tmq * mk[q];
    }
    *(float2*)(out + OUT_TOPK + b * Nc + n0) = make_float2(tmv[0], tmv[1]);
    float csum = bsum1024(lc, s_wf);
    float invden = 1.f / fmaxf(csum, 1.f);
    *(float2*)(g_poolw + ((size_t)b * 5 + 0) * Nc + n0) =
        make_float2(mk[0] * inv_mean, mk[1] * inv_mean);
    *(float2*)(g_poolw + ((size_t)b * 5 + 1) * Nc + n0) =
        make_float2(tmv[0] * mk[0] * invden, tmv[1] * mk[1] * invden);

    float sc3[3][2];
    float lm[3] = {-3e38f, -3e38f, -3e38f};
    #pragma unroll
    for (int k = 0; k < 3; k++) {
        float2 s2 = *(const float2*)(g_scores + (size_t)(1 + k) * Mc + b * Nc + n0);
        float sv[2] = {s2.x, s2.y};
        #pragma unroll
        for (int q = 0; q < 2; q++) {
            if (mk[q] == 0.f) sv[q] = NEG_INF_F;
            sc3[k][q] = sv[q];
            lm[k] = fmaxf(lm[k], sv[q]);
        }
    }
    bmaxv<3>(lm, s_wf);
    float ls[3] = {0.f, 0.f, 0.f};
    #pragma unroll
    for (int k = 0; k < 3; k++)
        #pragma unroll
        for (int q = 0; q < 2; q++) {
            sc3[k][q] = expf(sc3[k][q] - lm[k]);
            ls[k] += sc3[k][q];
        }
    bsumv<3>(ls, s_wf);

    float avq[2] = {0.f, 0.f};
    #pragma unroll
    for (int k = 0; k < 3; k++) {
        float inv = 1.f / ls[k];
        float a0 = (mk[0] == 0.f) ? 0.f : sc3[k][0] * inv;
        float a1 = (mk[1] == 0.f) ? 0.f : sc3[k][1] * inv;
        *(float2*)(out + OUT_ALLA + ((size_t)b * NBc + k) * Nc + n0) = make_float2(a0, a1);
        *(float2*)(g_poolw + ((size_t)b * 5 + 2 + k) * Nc + n0) = make_float2(a0, a1);
        avq[0] += a0;
        avq[1] += a1;
    }
    #pragma unroll
    for (int q = 0; q < 2; q++) avq[q] *= (1.f / 3.f);

    float es[2] = {0.f, 0.f};
    *(float2*)(out + OUT_AVG + b * Nc + n0) = make_float2(avq[0], avq[1]);
    #pragma unroll
    for (int q = 0; q < 2; q++) {
        es[0] += avq[q] * logf(avq[q] + 1e-8f);
        es[1] += avq[q] * avq[q];
        s_key[n0 + q] = f2key(avq[q]);
    }
    bsumv<2>(es, s_wf);   // also fences s_key writes
    if (t == 0) {
        out[OUT_ENT + b] = -es[0];
        out[OUT_EFF + b] = 1.f / es[1];
    }
    __syncthreads();

    unsigned T5 = radix1024(s_key, K5, s_hist, s_bc);
    int lg5 = 0;
    float lsum5 = 0.f;
    #pragma unroll
    for (int q = 0; q < 2; q++) {
        unsigned u = s_key[n0 + q];
        if (u > T5) { lg5++; lsum5 += avq[q]; }
    }
    int cg5 = bisum1024(lg5, s_wi);
    float sgt = bsum1024(lsum5, s_wf);
    if (t == 0)
        out[OUT_T5 + b] = sgt + (float)(K5 - cg5) * key2f(T5);
}

// ---------------- K3: pooling (exact R8/R11 version) ----------------
__global__ void __launch_bounds__(256) k_pool2(const float* __restrict__ X) {
    const int b = blockIdx.x >> 3;
    const int seg = blockIdx.x & 7;
    const int tid = threadIdx.x;
    const int tx = tid & 63;
    const int rg = tid >> 6;
    __shared__ float sw[5][256];
    __shared__ float part[4][5][256];

    #pragma unroll
    for (int p = 0; p < 5; p++)
        sw[p][tid] = g_poolw[((size_t)b * 5 + p) * Nc + seg * 256 + tid];
    __syncthreads();

    const float* xb = X + ((size_t)(b * Nc + seg * 256 + rg * 64)) * Dc + tx * 4;
    float4 a0 = {0,0,0,0}, a1 = {0,0,0,0}, a2 = {0,0,0,0}, a3 = {0,0,0,0}, a4 = {0,0,0,0};
    #pragma unroll 4
    for (int n = 0; n < 64; n++) {
        float4 xv = *(const float4*)(xb + (size_t)n * Dc);
        float w0 = sw[0][rg * 64 + n], w1 = sw[1][rg * 64 + n], w2 = sw[2][rg * 64 + n];
        float w3 = sw[3][rg * 64 + n], w4 = sw[4][rg * 64 + n];
        a0.x = fmaf(xv.x, w0, a0.x); a0.y = fmaf(xv.y, w0, a0.y);
        a0.z = fmaf(xv.z, w0, a0.z); a0.w = fmaf(xv.w, w0, a0.w);
        a1.x = fmaf(xv.x, w1, a1.x); a1.y = fmaf(xv.y, w1, a1.y);
        a1.z = fmaf(xv.z, w1, a1.z); a1.w = fmaf(xv.w, w1, a1.w);
        a2.x = fmaf(xv.x, w2, a2.x); a2.y = fmaf(xv.y, w2, a2.y);
        a2.z = fmaf(xv.z, w2, a2.z); a2.w = fmaf(xv.w, w2, a2.w);
        a3.x = fmaf(xv.x, w3, a3.x); a3.y = fmaf(xv.y, w3, a3.y);
        a3.z = fmaf(xv.z, w3, a3.z); a3.w = fmaf(xv.w, w3, a3.w);
        a4.x = fmaf(xv.x, w4, a4.x); a4.y = fmaf(xv.y, w4, a4.y);
        a4.z = fmaf(xv.z, w4, a4.z); a4.w = fmaf(xv.w, w4, a4.w);
    }
    *(float4*)&part[rg][0][tx * 4] = a0;
    *(float4*)&part[rg][1][tx * 4] = a1;
    *(float4*)&part[rg][2][tx * 4] = a2;
    *(float4*)&part[rg][3][tx * 4] = a3;
    *(float4*)&part[rg][4][tx * 4] = a4;
    __syncthreads();

    float* dst = g_poolpart + ((size_t)(b * NSEG + seg)) * 1280;
    #pragma unroll
    for (int p = 0; p < 5; p++) {
        float s = part[0][p][tid] + part[1][p][tid] + part[2][p][tid] + part[3][p][tid];
        dst[p * 256 + tid] = s;
    }
}

// ---------------- K4a: fusion GEMV1 partials (2 batch rows per block) ----------------
__global__ void __launch_bounds__(512) k_fuse1(const float* __restrict__ Wf1) {
    const int bp = blockIdx.x >> 2;
    const int seg = blockIdx.x & 3;
    const int c = threadIdx.x;
    const int b0 = bp * 2, b1 = b0 + 1;
    __shared__ float sc0[320];
    __shared__ float sc1[320];

    for (int i = c; i < 320; i += 512) {
        int gi = seg * 320 + i;
        float s0 = 0.f, s1 = 0.f;
        #pragma unroll
        for (int se = 0; se < NSEG; se++) {
            s0 += g_poolpart[((size_t)(b0 * NSEG + se)) * 1280 + gi];
            s1 += g_poolpart[((size_t)(b1 * NSEG + se)) * 1280 + gi];
        }
        sc0[i] = s0;
        sc1[i] = s1;
    }
    __syncthreads();

    float acc0 = 0.f, acc1 = 0.f;
    const float* W = Wf1 + (size_t)(seg * 320) * TWOD + c;
    #pragma unroll 8
    for (int j = 0; j < 320; j++) {
        float w = W[(size_t)j * TWOD];
        acc0 = fmaf(sc0[j], w, acc0);
        acc1 = fmaf(sc1[j], w, acc1);
    }
    g_fpart[(b0 * 4 + seg) * TWOD + c] = acc0;
    g_fpart[(b1 * 4 + seg) * TWOD + c] = acc1;
}

// ---------------- K4b: reduce + LN + GELU + GEMV2 (2 batch rows per block) ----------------
__global__ void __launch_bounds__(512) k_fuse2(const float* __restrict__ bf1,
                                               const float* __restrict__ lng,
                                               const float* __restrict__ lnb,
                                               const float* __restrict__ Wf2,
                                               const float* __restrict__ bf2,
                                               float* __restrict__ out) {
    const int bp = blockIdx.x;
    const int c = threadIdx.x;
    const int b0 = bp * 2, b1 = b0 + 1;
    __shared__ float sx0[TWOD];
    __shared__ float sx1[TWOD];
    __shared__ float red[TWOD];

    float bb = bf1[c];
    float acc0 = bb, acc1 = bb;
    #pragma unroll
    for (int seg = 0; seg < 4; seg++) {
        acc0 += g_fpart[(b0 * 4 + seg) * TWOD + c];
        acc1 += g_fpart[(b1 * 4 + seg) * TWOD + c];
    }

    float gln = lng[c], bln = lnb[c];

    red[c] = acc0; __syncthreads();
    #pragma unroll
    for (int s = 256; s > 0; s >>= 1) { if (c < s) red[c] += red[c + s]; __syncthreads(); }
    float mu0 = red[0] / (float)TWOD;
    __syncthreads();
    float dv0 = acc0 - mu0;
    red[c] = dv0 * dv0; __syncthreads();
    #pragma unroll
    for (int s = 256; s > 0; s >>= 1) { if (c < s) red[c] += red[c + s]; __syncthreads(); }
    float var0 = red[0] / (float)TWOD;
    __syncthreads();
    float x0 = dv0 * rsqrtf(var0 + 1e-5f) * gln + bln;
    sx0[c] = 0.5f * x0 * (1.f + erff(x0 * 0.70710678118654752f));

    red[c] = acc1; __syncthreads();
    #pragma unroll
    for (int s = 256; s > 0; s >>= 1) { if (c < s) red[c] += red[c + s]; __syncthreads(); }
    float mu1 = red[0] / (float)TWOD;
    __syncthreads();
    float dv1 = acc1 - mu1;
    red[c] = dv1 * dv1; __syncthreads();
    #pragma unroll
    for (int s = 256; s > 0; s >>= 1) { if (c < s) red[c] += red[c + s]; __syncthreads(); }
    float var1 = red[0] / (float)TWOD;
    __syncthreads();
    float x1 = dv1 * rsqrtf(var1 + 1e-5f) * gln + bln;
    sx1[c] = 0.5f * x1 * (1.f + erff(x1 * 0.70710678118654752f));
    __syncthreads();

    float o0 = bf2[c], o1 = o0;
    #pragma unroll 8
    for (int j = 0; j < TWOD; j++) {
        float w = Wf2[(size_t)j * TWOD + c];
        o0 = fmaf(sx0[j], w, o0);
        o1 = fmaf(sx1[j], w, o1);
    }
    out[OUT_BAG + b0 * TWOD + c] = o0;
    out[OUT_BAG + b1 * TWOD + c] = o1;
}

// ---------------- launch ----------------
extern "C" void kernel_launch(void* const* d_in, const int* in_sizes, int n_in,
                              void* d_out, int out_size) {
    const float* inst = (const float*)d_in[0];
    const float* mask = (const float*)d_in[1];
    const float* Ws1 = (const float*)d_in[2];
    const float* bs1 = (const float*)d_in[3];
    const float* Ws2 = (const float*)d_in[4];
    const float* bs2 = (const float*)d_in[5];
    const float* Wa1 = (const float*)d_in[6];
    const float* ba1 = (const float*)d_in[7];
    const float* Wa2 = (const float*)d_in[8];
    const float* ba2 = (const float*)d_in[9];
    const float* Wf1 = (const float*)d_in[10];
    const float* bf1 = (const float*)d_in[11];
    const float* lng = (const float*)d_in[12];
    const float* lnb = (const float*)d_in[13];
    const float* Wf2 = (const float*)d_in[14];
    const float* bf2 = (const float*)d_in[15];
    float* out = (float*)d_out;

    static bool attr_done = false;
    if (!attr_done) {
        cudaFuncSetAttribute(k_gemm_mma, cudaFuncAttributeMaxDynamicSharedMemorySize, SMEM_DYN);
        attr_done = true;
    }

    k_prep<<<321, 256>>>(Ws1, Wa1, bs1, Ws2, bs2, ba1, Wa2, ba2);
    k_gemm_mma<<<dim3(2, Mc / 128), 256, SMEM_DYN>>>(inst);
    k_perbatch<<<Bc, 1024>>>(mask, out);
    k_pool2<<<Bc * NSEG, 256>>>(inst);
    k_fuse1<<<(Bc / 2) * 4, 512>>>(Wf1);
    k_fuse2<<<Bc / 2, 512>>>(bf1, lng, lnb, Wf2, bf2, out);
}